// round 2
// baseline (speedup 1.0000x reference)
#include <cuda_runtime.h>
#include <math.h>

#define DIM   128
#define HEADS 4
#define HD    32
#define NTOK  128
#define BWIN  2048
#define NMASK 256
#define SCALEF 0.1767766952966369f   // 32^-0.5

// ---------------- device scratch (no runtime allocation allowed) ----------------
__device__ float g_cmask[NMASK * NTOK * NTOK];                  // 16 MB  (mask + sp_mask, index b%256)
__device__ float g_rpb[HEADS * NTOK * NTOK];                    // 256 KB (gathered rel-pos bias)
__device__ float g_q[(size_t)BWIN * HEADS * NTOK * HD];         // 128 MB
__device__ float g_k[(size_t)BWIN * HEADS * NTOK * HD];         // 128 MB
__device__ float g_v[(size_t)BWIN * HEADS * NTOK * HD];         // 128 MB
__device__ float g_ctx[(size_t)BWIN * NTOK * DIM];              // 128 MB

// ---------------- prep kernels ----------------
__global__ void prep_cmask_kernel(const float* __restrict__ mask,
                                  const float* __restrict__ sp_mask) {
    int i = (blockIdx.x * 256 + threadIdx.x) * 4;   // 4096 blocks cover 4,194,304 elems
    float4 a = *(const float4*)(mask + i);
    float4 b = *(const float4*)(sp_mask + i);
    float4 o;
    o.x = a.x + b.x; o.y = a.y + b.y; o.z = a.z + b.z; o.w = a.w + b.w;
    *(float4*)(g_cmask + i) = o;
}

__global__ void prep_rpb_kernel(const int* __restrict__ rpi,
                                const float* __restrict__ bias_table) {
    int i = blockIdx.x * 256 + threadIdx.x;          // 64 blocks * 256 = 16384
    int t = rpi[i];
#pragma unroll
    for (int h = 0; h < HEADS; ++h)
        g_rpb[h * NTOK * NTOK + i] = bias_table[t * HEADS + h];
}

// ---------------- QKV projection: per (window b, s in {q,k,v}) ----------------
// out[t][o] = sum_c x[b][t][c] * w_qkv[s*128+o][c] + b_qkv[s*128+o]   (q scaled)
// smem: xsT[64][128] (K-chunk transposed), wsT[64][128]  -> 64 KB, 2 CTAs/SM
__global__ __launch_bounds__(256, 2)
void qkv_kernel(const float* __restrict__ x,
                const float* __restrict__ w_qkv,
                const float* __restrict__ b_qkv) {
    int b = blockIdx.x;
    int s = blockIdx.y;                  // 0=q, 1=k, 2=v
    extern __shared__ float sm[];
    float* xsT = sm;                     // [cc][t]  cc in chunk of 64
    float* wsT = sm + 64 * NTOK;         // [cc][o]

    const float* xb = x + (size_t)b * NTOK * DIM;
    const float* wb = w_qkv + s * DIM * DIM;

    int tid = threadIdx.x;
    int ty = tid >> 4, tx = tid & 15;
    int r0 = ty * 8, c0 = tx * 8;

    float acc[8][8];
#pragma unroll
    for (int i = 0; i < 8; ++i)
#pragma unroll
        for (int j = 0; j < 8; ++j) acc[i][j] = 0.f;

    for (int cb = 0; cb < DIM; cb += 64) {
        __syncthreads();
        // load x chunk transposed: xsT[cc][t] = x[t][cb+cc]
        for (int i2 = tid * 4; i2 < NTOK * 64; i2 += 256 * 4) {
            int t = i2 >> 6, cc = i2 & 63;
            float4 v = *(const float4*)(xb + t * DIM + cb + cc);
            xsT[(cc + 0) * NTOK + t] = v.x;
            xsT[(cc + 1) * NTOK + t] = v.y;
            xsT[(cc + 2) * NTOK + t] = v.z;
            xsT[(cc + 3) * NTOK + t] = v.w;
        }
        // load w chunk transposed: wsT[cc][o] = w[o][cb+cc]
        for (int i2 = tid * 4; i2 < DIM * 64; i2 += 256 * 4) {
            int o = i2 >> 6, cc = i2 & 63;
            float4 v = *(const float4*)(wb + o * DIM + cb + cc);
            wsT[(cc + 0) * DIM + o] = v.x;
            wsT[(cc + 1) * DIM + o] = v.y;
            wsT[(cc + 2) * DIM + o] = v.z;
            wsT[(cc + 3) * DIM + o] = v.w;
        }
        __syncthreads();
#pragma unroll 4
        for (int c = 0; c < 64; ++c) {
            float a[8], w8[8];
            *(float4*)(a)     = *(const float4*)(xsT + c * NTOK + r0);
            *(float4*)(a + 4) = *(const float4*)(xsT + c * NTOK + r0 + 4);
            *(float4*)(w8)     = *(const float4*)(wsT + c * DIM + c0);
            *(float4*)(w8 + 4) = *(const float4*)(wsT + c * DIM + c0 + 4);
#pragma unroll
            for (int i = 0; i < 8; ++i)
#pragma unroll
                for (int j = 0; j < 8; ++j)
                    acc[i][j] = fmaf(a[i], w8[j], acc[i][j]);
        }
    }

    float scale = (s == 0) ? SCALEF : 1.0f;
    float* gout = (s == 0) ? g_q : (s == 1) ? g_k : g_v;
#pragma unroll
    for (int i = 0; i < 8; ++i) {
        int t = r0 + i;
#pragma unroll
        for (int j0 = 0; j0 < 8; j0 += 4) {
            int o = c0 + j0;
            int hh = o >> 5, d = o & 31;
            float4 v;
            v.x = (acc[i][j0 + 0] + b_qkv[s * DIM + o + 0]) * scale;
            v.y = (acc[i][j0 + 1] + b_qkv[s * DIM + o + 1]) * scale;
            v.z = (acc[i][j0 + 2] + b_qkv[s * DIM + o + 2]) * scale;
            v.w = (acc[i][j0 + 3] + b_qkv[s * DIM + o + 3]) * scale;
            *(float4*)(gout + (((size_t)b * HEADS + hh) * NTOK + t) * HD + d) = v;
        }
    }
}

// ---------------- attention: per (window b, head h) ----------------
// S = q k^T + cmask[b%256] + rpb[h]; softmax rows; ctx_h = P v
// smem: qsT[32][128], ksT[32][128], vs[128][32], P[128][129]  = 115200 B, 2 CTAs/SM
__global__ __launch_bounds__(256, 2)
void att_kernel() {
    int b = blockIdx.x, h = blockIdx.y;
    extern __shared__ float sm[];
    float* qsT = sm;                      // [d][t]
    float* ksT = sm + 32 * NTOK;          // [d][t]
    float* vs  = sm + 2 * 32 * NTOK;      // [t][d]
    float* P   = sm + 3 * 32 * NTOK;      // [r][j], stride 129

    int tid = threadIdx.x;
    const float* gq = g_q + ((size_t)b * HEADS + h) * NTOK * HD;
    const float* gk = g_k + ((size_t)b * HEADS + h) * NTOK * HD;
    const float* gv = g_v + ((size_t)b * HEADS + h) * NTOK * HD;

    // load q,k transposed; v natural
    for (int i = tid * 4; i < NTOK * HD; i += 256 * 4) {
        int t = i >> 5, d = i & 31;
        float4 a = *(const float4*)(gq + i);
        qsT[(d + 0) * NTOK + t] = a.x;
        qsT[(d + 1) * NTOK + t] = a.y;
        qsT[(d + 2) * NTOK + t] = a.z;
        qsT[(d + 3) * NTOK + t] = a.w;
        float4 kk = *(const float4*)(gk + i);
        ksT[(d + 0) * NTOK + t] = kk.x;
        ksT[(d + 1) * NTOK + t] = kk.y;
        ksT[(d + 2) * NTOK + t] = kk.z;
        ksT[(d + 3) * NTOK + t] = kk.w;
        *(float4*)(vs + i) = *(const float4*)(gv + i);
    }
    __syncthreads();

    int ty = tid >> 4, tx = tid & 15;
    int r0 = ty * 8, c0 = tx * 8;

    float acc[8][8];
#pragma unroll
    for (int i = 0; i < 8; ++i)
#pragma unroll
        for (int j = 0; j < 8; ++j) acc[i][j] = 0.f;

#pragma unroll 8
    for (int d = 0; d < HD; ++d) {
        float a[8], kk[8];
        *(float4*)(a)      = *(const float4*)(qsT + d * NTOK + r0);
        *(float4*)(a + 4)  = *(const float4*)(qsT + d * NTOK + r0 + 4);
        *(float4*)(kk)     = *(const float4*)(ksT + d * NTOK + c0);
        *(float4*)(kk + 4) = *(const float4*)(ksT + d * NTOK + c0 + 4);
#pragma unroll
        for (int i = 0; i < 8; ++i)
#pragma unroll
            for (int j = 0; j < 8; ++j)
                acc[i][j] = fmaf(a[i], kk[j], acc[i][j]);
    }

    // additive biases (L2-resident)
    const float* cm = g_cmask + (size_t)(b & (NMASK - 1)) * NTOK * NTOK;
    const float* rp = g_rpb + (size_t)h * NTOK * NTOK;
#pragma unroll
    for (int i = 0; i < 8; ++i) {
        const float* cmr = cm + (r0 + i) * NTOK + c0;
        const float* rpr = rp + (r0 + i) * NTOK + c0;
        float4 m0 = *(const float4*)(cmr);
        float4 m1 = *(const float4*)(cmr + 4);
        float4 p0 = *(const float4*)(rpr);
        float4 p1 = *(const float4*)(rpr + 4);
        acc[i][0] += m0.x + p0.x;  acc[i][1] += m0.y + p0.y;
        acc[i][2] += m0.z + p0.z;  acc[i][3] += m0.w + p0.w;
        acc[i][4] += m1.x + p1.x;  acc[i][5] += m1.y + p1.y;
        acc[i][6] += m1.z + p1.z;  acc[i][7] += m1.w + p1.w;
    }

    // softmax: each row split across 16 tx-lanes (contiguous 16-lane groups)
#pragma unroll
    for (int i = 0; i < 8; ++i) {
        float mx = acc[i][0];
#pragma unroll
        for (int j = 1; j < 8; ++j) mx = fmaxf(mx, acc[i][j]);
#pragma unroll
        for (int o = 8; o > 0; o >>= 1)
            mx = fmaxf(mx, __shfl_xor_sync(0xffffffffu, mx, o));
        float ssum = 0.f;
#pragma unroll
        for (int j = 0; j < 8; ++j) {
            acc[i][j] = __expf(acc[i][j] - mx);
            ssum += acc[i][j];
        }
#pragma unroll
        for (int o = 8; o > 0; o >>= 1)
            ssum += __shfl_xor_sync(0xffffffffu, ssum, o);
        float inv = 1.0f / ssum;
#pragma unroll
        for (int j = 0; j < 8; ++j)
            P[(r0 + i) * 129 + c0 + j] = acc[i][j] * inv;
    }
    __syncthreads();

    // PV: thread pair per row; 16 output channels each
    int r = tid >> 1;
    int d0 = (tid & 1) * 16;
    float out[16];
#pragma unroll
    for (int q = 0; q < 16; ++q) out[q] = 0.f;
    const float* Pr = P + r * 129;
#pragma unroll 4
    for (int j = 0; j < NTOK; ++j) {
        float pv = Pr[j];
        const float* vr = vs + j * HD + d0;
        float4 v0 = *(const float4*)(vr);
        float4 v1 = *(const float4*)(vr + 4);
        float4 v2 = *(const float4*)(vr + 8);
        float4 v3 = *(const float4*)(vr + 12);
        out[0]  = fmaf(pv, v0.x, out[0]);   out[1]  = fmaf(pv, v0.y, out[1]);
        out[2]  = fmaf(pv, v0.z, out[2]);   out[3]  = fmaf(pv, v0.w, out[3]);
        out[4]  = fmaf(pv, v1.x, out[4]);   out[5]  = fmaf(pv, v1.y, out[5]);
        out[6]  = fmaf(pv, v1.z, out[6]);   out[7]  = fmaf(pv, v1.w, out[7]);
        out[8]  = fmaf(pv, v2.x, out[8]);   out[9]  = fmaf(pv, v2.y, out[9]);
        out[10] = fmaf(pv, v2.z, out[10]);  out[11] = fmaf(pv, v2.w, out[11]);
        out[12] = fmaf(pv, v3.x, out[12]);  out[13] = fmaf(pv, v3.y, out[13]);
        out[14] = fmaf(pv, v3.z, out[14]);  out[15] = fmaf(pv, v3.w, out[15]);
    }
    float* go = g_ctx + ((size_t)b * NTOK + r) * DIM + h * HD + d0;
    *(float4*)(go)      = make_float4(out[0], out[1], out[2], out[3]);
    *(float4*)(go + 4)  = make_float4(out[4], out[5], out[6], out[7]);
    *(float4*)(go + 8)  = make_float4(out[8], out[9], out[10], out[11]);
    *(float4*)(go + 12) = make_float4(out[12], out[13], out[14], out[15]);
}

// ---------------- output projection: out = ctx @ w_proj^T + b_proj ----------------
__global__ __launch_bounds__(256, 2)
void proj_kernel(const float* __restrict__ w_proj,
                 const float* __restrict__ b_proj,
                 float* __restrict__ out) {
    int b = blockIdx.x;
    extern __shared__ float sm[];
    float* xsT = sm;                     // [cc][t]
    float* wsT = sm + 64 * NTOK;         // [cc][j]

    const float* xb = g_ctx + (size_t)b * NTOK * DIM;

    int tid = threadIdx.x;
    int ty = tid >> 4, tx = tid & 15;
    int r0 = ty * 8, c0 = tx * 8;

    float acc[8][8];
#pragma unroll
    for (int i = 0; i < 8; ++i)
#pragma unroll
        for (int j = 0; j < 8; ++j) acc[i][j] = 0.f;

    for (int cb = 0; cb < DIM; cb += 64) {
        __syncthreads();
        for (int i2 = tid * 4; i2 < NTOK * 64; i2 += 256 * 4) {
            int t = i2 >> 6, cc = i2 & 63;
            float4 v = *(const float4*)(xb + t * DIM + cb + cc);
            xsT[(cc + 0) * NTOK + t] = v.x;
            xsT[(cc + 1) * NTOK + t] = v.y;
            xsT[(cc + 2) * NTOK + t] = v.z;
            xsT[(cc + 3) * NTOK + t] = v.w;
        }
        for (int i2 = tid * 4; i2 < DIM * 64; i2 += 256 * 4) {
            int o = i2 >> 6, cc = i2 & 63;
            float4 v = *(const float4*)(w_proj + o * DIM + cb + cc);
            wsT[(cc + 0) * DIM + o] = v.x;
            wsT[(cc + 1) * DIM + o] = v.y;
            wsT[(cc + 2) * DIM + o] = v.z;
            wsT[(cc + 3) * DIM + o] = v.w;
        }
        __syncthreads();
#pragma unroll 4
        for (int c = 0; c < 64; ++c) {
            float a[8], w8[8];
            *(float4*)(a)     = *(const float4*)(xsT + c * NTOK + r0);
            *(float4*)(a + 4) = *(const float4*)(xsT + c * NTOK + r0 + 4);
            *(float4*)(w8)     = *(const float4*)(wsT + c * DIM + c0);
            *(float4*)(w8 + 4) = *(const float4*)(wsT + c * DIM + c0 + 4);
#pragma unroll
            for (int i = 0; i < 8; ++i)
#pragma unroll
                for (int j = 0; j < 8; ++j)
                    acc[i][j] = fmaf(a[i], w8[j], acc[i][j]);
        }
    }

#pragma unroll
    for (int i = 0; i < 8; ++i) {
        int t = r0 + i;
#pragma unroll
        for (int j0 = 0; j0 < 8; j0 += 4) {
            int o = c0 + j0;
            float4 v;
            v.x = acc[i][j0 + 0] + b_proj[o + 0];
            v.y = acc[i][j0 + 1] + b_proj[o + 1];
            v.z = acc[i][j0 + 2] + b_proj[o + 2];
            v.w = acc[i][j0 + 3] + b_proj[o + 3];
            *(float4*)(out + ((size_t)b * NTOK + t) * DIM + o) = v;
        }
    }
}

// ---------------- launch ----------------
extern "C" void kernel_launch(void* const* d_in, const int* in_sizes, int n_in,
                              void* d_out, int out_size) {
    const float* x          = (const float*)d_in[0];
    const int*   rpi        = (const int*)d_in[1];
    const float* mask       = (const float*)d_in[2];
    const float* sp_mask    = (const float*)d_in[3];
    const float* w_qkv      = (const float*)d_in[4];
    const float* b_qkv      = (const float*)d_in[5];
    const float* bias_table = (const float*)d_in[6];
    const float* w_proj     = (const float*)d_in[7];
    const float* b_proj     = (const float*)d_in[8];
    float* out = (float*)d_out;

    const int QKV_SMEM  = 64 * 128 * 4 * 2;                     // 65536
    const int ATT_SMEM  = (3 * 32 * 128 + 128 * 129) * 4;       // 115200
    const int PROJ_SMEM = QKV_SMEM;

    cudaFuncSetAttribute((const void*)qkv_kernel,
                         cudaFuncAttributeMaxDynamicSharedMemorySize, QKV_SMEM);
    cudaFuncSetAttribute((const void*)att_kernel,
                         cudaFuncAttributeMaxDynamicSharedMemorySize, ATT_SMEM);
    cudaFuncSetAttribute((const void*)proj_kernel,
                         cudaFuncAttributeMaxDynamicSharedMemorySize, PROJ_SMEM);

    prep_cmask_kernel<<<4096, 256>>>(mask, sp_mask);
    prep_rpb_kernel<<<64, 256>>>(rpi, bias_table);
    qkv_kernel<<<dim3(BWIN, 3), 256, QKV_SMEM>>>(x, w_qkv, b_qkv);
    att_kernel<<<dim3(BWIN, HEADS), 256, ATT_SMEM>>>();
    proj_kernel<<<BWIN, 256, PROJ_SMEM>>>(w_proj, b_proj, out);
}

// round 4
// speedup vs baseline: 1.6541x; 1.6541x over previous
#include <cuda_runtime.h>
#include <cuda_bf16.h>
#include <stdint.h>

#define DIM   128
#define HEADS 4
#define HD    32
#define NTOK  128
#define BWIN  2048
#define NMASK 256
#define SCALEF 0.1767766952966369f
#define PAD   136   // bf16 elements per smem row (272B stride: conflict-free ldmatrix)

__device__ float g_cmask[NMASK * NTOK * NTOK];
__device__ float g_rpb[HEADS * NTOK * NTOK];
__device__ float g_q[(size_t)BWIN * HEADS * NTOK * HD];
__device__ float g_k[(size_t)BWIN * HEADS * NTOK * HD];
__device__ float g_v[(size_t)BWIN * HEADS * NTOK * HD];
__device__ float g_ctx[(size_t)BWIN * NTOK * DIM];
// preconverted weights, row-major [rows][128] bf16 as uint4 (8 bf16 each)
__device__ uint4 g_wqkv_h[6144], g_wqkv_l[6144];   // 384 rows
__device__ uint4 g_wproj_h[2048], g_wproj_l[2048]; // 128 rows

// ---------- helpers ----------
__device__ __forceinline__ uint32_t smem_u32(const void* p) {
    uint32_t a;
    asm("{ .reg .u64 t; cvta.to.shared.u64 t, %1; cvt.u32.u64 %0, t; }" : "=r"(a) : "l"(p));
    return a;
}
__device__ __forceinline__ uint32_t pk2(float a, float b) {
    __nv_bfloat162 t = __floats2bfloat162_rn(a, b);
    return *reinterpret_cast<uint32_t*>(&t);
}
#define LDM4(r, addr) \
    asm volatile("ldmatrix.sync.aligned.m8n8.x4.shared.b16 {%0,%1,%2,%3}, [%4];" \
                 : "=r"((r)[0]), "=r"((r)[1]), "=r"((r)[2]), "=r"((r)[3]) : "r"(addr))
#define LDM2(r0, r1, addr) \
    asm volatile("ldmatrix.sync.aligned.m8n8.x2.shared.b16 {%0,%1}, [%2];" \
                 : "=r"(r0), "=r"(r1) : "r"(addr))
#define MMA(d, a, b0, b1) \
    asm volatile("mma.sync.aligned.m16n8k16.row.col.f32.bf16.bf16.f32 " \
                 "{%0,%1,%2,%3}, {%4,%5,%6,%7}, {%8,%9}, {%0,%1,%2,%3};" \
                 : "+f"((d)[0]), "+f"((d)[1]), "+f"((d)[2]), "+f"((d)[3]) \
                 : "r"((a)[0]), "r"((a)[1]), "r"((a)[2]), "r"((a)[3]), "r"(b0), "r"(b1))

// smem offsets (bytes): XH[0] XL[34816] WH[69632] WL[87040]; total 104448
#define SM_XL 34816
#define SM_WH 69632
#define SM_WL 87040
#define MMA_SMEM 104448

// ---------- prep ----------
__global__ void prep_cmask_kernel(const float* __restrict__ m, const float* __restrict__ s) {
    int i = (blockIdx.x * 256 + threadIdx.x) * 4;
    float4 a = *(const float4*)(m + i), b = *(const float4*)(s + i);
    *(float4*)(g_cmask + i) = make_float4(a.x + b.x, a.y + b.y, a.z + b.z, a.w + b.w);
}
__global__ void prep_rpb_kernel(const int* __restrict__ rpi, const float* __restrict__ bt) {
    int i = blockIdx.x * 256 + threadIdx.x;
    int t = rpi[i];
#pragma unroll
    for (int h = 0; h < HEADS; ++h) g_rpb[h * NTOK * NTOK + i] = bt[t * HEADS + h];
}
__global__ void conv_w_kernel(const float* __restrict__ w, int n, int which) {
    int i = blockIdx.x * 256 + threadIdx.x;
    if (i >= n) return;
    int row = i >> 4, c0 = (i & 15) * 8;
    const float* wr = w + row * DIM + c0;
    float4 v0 = *(const float4*)(wr), v1 = *(const float4*)(wr + 4);
    float h0 = __bfloat162float(__float2bfloat16(v0.x)), h1 = __bfloat162float(__float2bfloat16(v0.y));
    float h2 = __bfloat162float(__float2bfloat16(v0.z)), h3 = __bfloat162float(__float2bfloat16(v0.w));
    float h4 = __bfloat162float(__float2bfloat16(v1.x)), h5 = __bfloat162float(__float2bfloat16(v1.y));
    float h6 = __bfloat162float(__float2bfloat16(v1.z)), h7 = __bfloat162float(__float2bfloat16(v1.w));
    uint4 hv = make_uint4(pk2(v0.x, v0.y), pk2(v0.z, v0.w), pk2(v1.x, v1.y), pk2(v1.z, v1.w));
    uint4 lv = make_uint4(pk2(v0.x - h0, v0.y - h1), pk2(v0.z - h2, v0.w - h3),
                          pk2(v1.x - h4, v1.y - h5), pk2(v1.z - h6, v1.w - h7));
    if (which == 0) { g_wqkv_h[i] = hv; g_wqkv_l[i] = lv; }
    else            { g_wproj_h[i] = hv; g_wproj_l[i] = lv; }
}

// ---------- GEMM pieces ----------
__device__ __forceinline__ void conv_A(const float* __restrict__ src, uint32_t XH, int tid) {
    for (int i = tid; i < 4096; i += 256) {
        int t = i >> 5, c = (i & 31) * 4;
        float4 v = *(const float4*)(src + t * DIM + c);
        float hx = __bfloat162float(__float2bfloat16(v.x)), hy = __bfloat162float(__float2bfloat16(v.y));
        float hz = __bfloat162float(__float2bfloat16(v.z)), hw = __bfloat162float(__float2bfloat16(v.w));
        uint32_t o = XH + (uint32_t)(t * PAD + c) * 2u;
        asm volatile("st.shared.v2.b32 [%0], {%1, %2};"
                     :: "r"(o), "r"(pk2(v.x, v.y)), "r"(pk2(v.z, v.w)));
        asm volatile("st.shared.v2.b32 [%0], {%1, %2};"
                     :: "r"(o + SM_XL), "r"(pk2(v.x - hx, v.y - hy)), "r"(pk2(v.z - hz, v.w - hw)));
    }
}
__device__ __forceinline__ void cp_W(const uint4* gh, const uint4* gl, uint32_t WH, int tid) {
    for (int i = tid; i < 1024; i += 256) {
        int row = i >> 4, c0 = (i & 15) * 8;
        uint32_t o = WH + (uint32_t)(row * PAD + c0) * 2u;
        uint4 a = __ldg(gh + i), c = __ldg(gl + i);
        asm volatile("st.shared.v4.b32 [%0], {%1,%2,%3,%4};"
                     :: "r"(o), "r"(a.x), "r"(a.y), "r"(a.z), "r"(a.w));
        asm volatile("st.shared.v4.b32 [%0], {%1,%2,%3,%4};"
                     :: "r"(o + (SM_WL - SM_WH)), "r"(c.x), "r"(c.y), "r"(c.z), "r"(c.w));
    }
}

// MODE 0: qkv epilogue (split q/k/v, scale q).  MODE 1: generic out + bias.
template <int NCHUNK, int MODE>
__device__ __forceinline__ void gemm_mma(const float* __restrict__ xsrc,
                                         const uint4* __restrict__ wh,
                                         const uint4* __restrict__ wl,
                                         const float* __restrict__ bias,
                                         float* __restrict__ gen_out, int b) {
    extern __shared__ unsigned char sraw[];
    uint32_t XH = smem_u32(sraw);
    uint32_t WH = XH + SM_WH;
    int tid = threadIdx.x, wid = tid >> 5, lane = tid & 31;

    conv_A(xsrc, XH, tid);

    int r0 = wid * 16;
    int lr = lane & 15, kh = (lane >> 4) & 1;         // A ldmatrix lane mapping
    int bl8 = lane & 7, bseg = (lane >> 3) & 1;       // B ldmatrix lane mapping
    uint32_t abase = XH + (uint32_t)((r0 + lr) * PAD + kh * 8) * 2u;
    uint32_t bbase = WH + (uint32_t)(bl8 * PAD + bseg * 8) * 2u;

    for (int ch = 0; ch < NCHUNK; ++ch) {
        __syncthreads();
        cp_W(wh + ch * 1024, wl + ch * 1024, WH, tid);
        __syncthreads();

        float acc[8][4];
#pragma unroll
        for (int nt = 0; nt < 8; ++nt)
#pragma unroll
            for (int j = 0; j < 4; ++j) acc[nt][j] = 0.f;

#pragma unroll
        for (int k = 0; k < 8; ++k) {
            uint32_t ah[4], al[4];
            uint32_t aa = abase + (uint32_t)(k * 32);
            LDM4(ah, aa);
            LDM4(al, aa + SM_XL);
#pragma unroll
            for (int nt = 0; nt < 8; ++nt) {
                uint32_t ba = bbase + (uint32_t)(nt * 8 * PAD * 2 + k * 32);
                uint32_t bh0, bh1, bl0, bl1;
                LDM2(bh0, bh1, ba);
                LDM2(bl0, bl1, ba + (SM_WL - SM_WH));
                MMA(acc[nt], ah, bh0, bh1);
                MMA(acc[nt], ah, bl0, bl1);
                MMA(acc[nt], al, bh0, bh1);
            }
        }

        int t0 = r0 + (lane >> 2);
#pragma unroll
        for (int nt = 0; nt < 8; ++nt) {
            int f = ch * 64 + nt * 8 + (lane & 3) * 2;
            float bx = __ldg(bias + f), by = __ldg(bias + f + 1);
            if (MODE == 0) {
                int s = f >> 7, h = (f >> 5) & 3, d = f & 31;
                float sc = (s == 0) ? SCALEF : 1.0f;
                float* dst = (s == 0 ? g_q : s == 1 ? g_k : g_v)
                           + ((size_t)b * HEADS + h) * NTOK * HD + d;
                *(float2*)(dst + (size_t)t0 * HD) =
                    make_float2((acc[nt][0] + bx) * sc, (acc[nt][1] + by) * sc);
                *(float2*)(dst + (size_t)(t0 + 8) * HD) =
                    make_float2((acc[nt][2] + bx) * sc, (acc[nt][3] + by) * sc);
            } else {
                *(float2*)(gen_out + ((size_t)b * NTOK + t0) * DIM + f) =
                    make_float2(acc[nt][0] + bx, acc[nt][1] + by);
                *(float2*)(gen_out + ((size_t)b * NTOK + t0 + 8) * DIM + f) =
                    make_float2(acc[nt][2] + bx, acc[nt][3] + by);
            }
        }
    }
}

__global__ __launch_bounds__(256, 2)
void qkv_mma_kernel(const float* __restrict__ x, const float* __restrict__ b_qkv) {
    gemm_mma<6, 0>(x + (size_t)blockIdx.x * NTOK * DIM, g_wqkv_h, g_wqkv_l, b_qkv,
                   nullptr, blockIdx.x);
}
__global__ __launch_bounds__(256, 2)
void proj_mma_kernel(const float* __restrict__ b_proj, float* __restrict__ out) {
    gemm_mma<2, 1>(g_ctx + (size_t)blockIdx.x * NTOK * DIM, g_wproj_h, g_wproj_l, b_proj,
                   out, blockIdx.x);
}

// ---------- attention (unchanged SIMT, known good) ----------
__global__ __launch_bounds__(256, 2)
void att_kernel() {
    int b = blockIdx.x, h = blockIdx.y;
    extern __shared__ float sm[];
    float* qsT = sm;
    float* ksT = sm + 32 * NTOK;
    float* vs  = sm + 2 * 32 * NTOK;
    float* P   = sm + 3 * 32 * NTOK;

    int tid = threadIdx.x;
    const float* gq = g_q + ((size_t)b * HEADS + h) * NTOK * HD;
    const float* gk = g_k + ((size_t)b * HEADS + h) * NTOK * HD;
    const float* gv = g_v + ((size_t)b * HEADS + h) * NTOK * HD;

    for (int i = tid * 4; i < NTOK * HD; i += 256 * 4) {
        int t = i >> 5, d = i & 31;
        float4 a = *(const float4*)(gq + i);
        qsT[(d + 0) * NTOK + t] = a.x; qsT[(d + 1) * NTOK + t] = a.y;
        qsT[(d + 2) * NTOK + t] = a.z; qsT[(d + 3) * NTOK + t] = a.w;
        float4 kk = *(const float4*)(gk + i);
        ksT[(d + 0) * NTOK + t] = kk.x; ksT[(d + 1) * NTOK + t] = kk.y;
        ksT[(d + 2) * NTOK + t] = kk.z; ksT[(d + 3) * NTOK + t] = kk.w;
        *(float4*)(vs + i) = *(const float4*)(gv + i);
    }
    __syncthreads();

    int ty = tid >> 4, tx = tid & 15;
    int r0 = ty * 8, c0 = tx * 8;
    float acc[8][8];
#pragma unroll
    for (int i = 0; i < 8; ++i)
#pragma unroll
        for (int j = 0; j < 8; ++j) acc[i][j] = 0.f;

#pragma unroll 8
    for (int d = 0; d < HD; ++d) {
        float a[8], kk[8];
        *(float4*)(a)      = *(const float4*)(qsT + d * NTOK + r0);
        *(float4*)(a + 4)  = *(const float4*)(qsT + d * NTOK + r0 + 4);
        *(float4*)(kk)     = *(const float4*)(ksT + d * NTOK + c0);
        *(float4*)(kk + 4) = *(const float4*)(ksT + d * NTOK + c0 + 4);
#pragma unroll
        for (int i = 0; i < 8; ++i)
#pragma unroll
            for (int j = 0; j < 8; ++j) acc[i][j] = fmaf(a[i], kk[j], acc[i][j]);
    }

    const float* cm = g_cmask + (size_t)(b & (NMASK - 1)) * NTOK * NTOK;
    const float* rp = g_rpb + (size_t)h * NTOK * NTOK;
#pragma unroll
    for (int i = 0; i < 8; ++i) {
        const float* cmr = cm + (r0 + i) * NTOK + c0;
        const float* rpr = rp + (r0 + i) * NTOK + c0;
        float4 m0 = *(const float4*)(cmr), m1 = *(const float4*)(cmr + 4);
        float4 p0 = *(const float4*)(rpr), p1 = *(const float4*)(rpr + 4);
        acc[i][0] += m0.x + p0.x;  acc[i][1] += m0.y + p0.y;
        acc[i][2] += m0.z + p0.z;  acc[i][3] += m0.w + p0.w;
        acc[i][4] += m1.x + p1.x;  acc[i][5] += m1.y + p1.y;
        acc[i][6] += m1.z + p1.z;  acc[i][7] += m1.w + p1.w;
    }

#pragma unroll
    for (int i = 0; i < 8; ++i) {
        float mx = acc[i][0];
#pragma unroll
        for (int j = 1; j < 8; ++j) mx = fmaxf(mx, acc[i][j]);
#pragma unroll
        for (int o = 8; o > 0; o >>= 1) mx = fmaxf(mx, __shfl_xor_sync(0xffffffffu, mx, o));
        float ssum = 0.f;
#pragma unroll
        for (int j = 0; j < 8; ++j) { acc[i][j] = __expf(acc[i][j] - mx); ssum += acc[i][j]; }
#pragma unroll
        for (int o = 8; o > 0; o >>= 1) ssum += __shfl_xor_sync(0xffffffffu, ssum, o);
        float inv = 1.0f / ssum;
#pragma unroll
        for (int j = 0; j < 8; ++j) P[(r0 + i) * 129 + c0 + j] = acc[i][j] * inv;
    }
    __syncthreads();

    int r = tid >> 1, d0 = (tid & 1) * 16;
    float out[16];
#pragma unroll
    for (int q = 0; q < 16; ++q) out[q] = 0.f;
    const float* Pr = P + r * 129;
#pragma unroll 4
    for (int j = 0; j < NTOK; ++j) {
        float pv = Pr[j];
        const float* vr = vs + j * HD + d0;
        float4 v0 = *(const float4*)(vr), v1 = *(const float4*)(vr + 4);
        float4 v2 = *(const float4*)(vr + 8), v3 = *(const float4*)(vr + 12);
        out[0]  = fmaf(pv, v0.x, out[0]);   out[1]  = fmaf(pv, v0.y, out[1]);
        out[2]  = fmaf(pv, v0.z, out[2]);   out[3]  = fmaf(pv, v0.w, out[3]);
        out[4]  = fmaf(pv, v1.x, out[4]);   out[5]  = fmaf(pv, v1.y, out[5]);
        out[6]  = fmaf(pv, v1.z, out[6]);   out[7]  = fmaf(pv, v1.w, out[7]);
        out[8]  = fmaf(pv, v2.x, out[8]);   out[9]  = fmaf(pv, v2.y, out[9]);
        out[10] = fmaf(pv, v2.z, out[10]);  out[11] = fmaf(pv, v2.w, out[11]);
        out[12] = fmaf(pv, v3.x, out[12]);  out[13] = fmaf(pv, v3.y, out[13]);
        out[14] = fmaf(pv, v3.z, out[14]);  out[15] = fmaf(pv, v3.w, out[15]);
    }
    float* go = g_ctx + ((size_t)b * NTOK + r) * DIM + h * HD + d0;
    *(float4*)(go)      = make_float4(out[0], out[1], out[2], out[3]);
    *(float4*)(go + 4)  = make_float4(out[4], out[5], out[6], out[7]);
    *(float4*)(go + 8)  = make_float4(out[8], out[9], out[10], out[11]);
    *(float4*)(go + 12) = make_float4(out[12], out[13], out[14], out[15]);
}

// ---------- launch ----------
extern "C" void kernel_launch(void* const* d_in, const int* in_sizes, int n_in,
                              void* d_out, int out_size) {
    const float* x          = (const float*)d_in[0];
    const int*   rpi        = (const int*)d_in[1];
    const float* mask       = (const float*)d_in[2];
    const float* sp_mask    = (const float*)d_in[3];
    const float* w_qkv      = (const float*)d_in[4];
    const float* b_qkv      = (const float*)d_in[5];
    const float* bias_table = (const float*)d_in[6];
    const float* w_proj     = (const float*)d_in[7];
    const float* b_proj     = (const float*)d_in[8];
    float* out = (float*)d_out;

    const int ATT_SMEM = (3 * 32 * NTOK + NTOK * 129) * 4;
    cudaFuncSetAttribute((const void*)qkv_mma_kernel,
                         cudaFuncAttributeMaxDynamicSharedMemorySize, MMA_SMEM);
    cudaFuncSetAttribute((const void*)proj_mma_kernel,
                         cudaFuncAttributeMaxDynamicSharedMemorySize, MMA_SMEM);
    cudaFuncSetAttribute((const void*)att_kernel,
                         cudaFuncAttributeMaxDynamicSharedMemorySize, ATT_SMEM);

    prep_cmask_kernel<<<4096, 256>>>(mask, sp_mask);
    prep_rpb_kernel<<<64, 256>>>(rpi, bias_table);
    conv_w_kernel<<<24, 256>>>(w_qkv, 6144, 0);
    conv_w_kernel<<<8, 256>>>(w_proj, 2048, 1);
    qkv_mma_kernel<<<BWIN, 256, MMA_SMEM>>>(x, b_qkv);
    att_kernel<<<dim3(BWIN, HEADS), 256, ATT_SMEM>>>();
    proj_mma_kernel<<<BWIN, 256, MMA_SMEM>>>(b_proj, out);
}

// round 5
// speedup vs baseline: 2.3069x; 1.3946x over previous
#include <cuda_runtime.h>
#include <cuda_bf16.h>
#include <stdint.h>

#define DIM   128
#define HEADS 4
#define HD    32
#define NTOK  128
#define BWIN  2048
#define NMASK 256
#define SCALEF 0.1767766952966369f
#define PAD   136

__device__ float g_cmask[NMASK * NTOK * NTOK];
__device__ float g_rpb[HEADS * NTOK * NTOK];
__device__ float g_q[(size_t)BWIN * HEADS * NTOK * HD];
__device__ float g_k[(size_t)BWIN * HEADS * NTOK * HD];
__device__ float g_v[(size_t)BWIN * HEADS * NTOK * HD];
__device__ float g_ctx[(size_t)BWIN * NTOK * DIM];
__device__ uint4 g_wqkv_h[6144], g_wqkv_l[6144];
__device__ uint4 g_wproj_h[2048], g_wproj_l[2048];

// ---------- helpers ----------
__device__ __forceinline__ uint32_t smem_u32(const void* p) {
    uint32_t a;
    asm("{ .reg .u64 t; cvta.to.shared.u64 t, %1; cvt.u32.u64 %0, t; }" : "=r"(a) : "l"(p));
    return a;
}
__device__ __forceinline__ uint32_t pk2(float a, float b) {
    __nv_bfloat162 t = __floats2bfloat162_rn(a, b);
    return *reinterpret_cast<uint32_t*>(&t);
}
__device__ __forceinline__ float bfh(float x) {
    return __bfloat162float(__float2bfloat16(x));
}
#define LDM4(r, addr) \
    asm volatile("ldmatrix.sync.aligned.m8n8.x4.shared.b16 {%0,%1,%2,%3}, [%4];" \
                 : "=r"((r)[0]), "=r"((r)[1]), "=r"((r)[2]), "=r"((r)[3]) : "r"(addr))
#define LDM2(r0, r1, addr) \
    asm volatile("ldmatrix.sync.aligned.m8n8.x2.shared.b16 {%0,%1}, [%2];" \
                 : "=r"(r0), "=r"(r1) : "r"(addr))
#define MMA(d, a, b0, b1) \
    asm volatile("mma.sync.aligned.m16n8k16.row.col.f32.bf16.bf16.f32 " \
                 "{%0,%1,%2,%3}, {%4,%5,%6,%7}, {%8,%9}, {%0,%1,%2,%3};" \
                 : "+f"((d)[0]), "+f"((d)[1]), "+f"((d)[2]), "+f"((d)[3]) \
                 : "r"((a)[0]), "r"((a)[1]), "r"((a)[2]), "r"((a)[3]), "r"(b0), "r"(b1))

#define SM_XL 34816
#define SM_WH 69632
#define SM_WL 87040
#define MMA_SMEM 104448

// ---------- prep ----------
__global__ void prep_cmask_kernel(const float* __restrict__ m, const float* __restrict__ s) {
    int i = (blockIdx.x * 256 + threadIdx.x) * 4;
    float4 a = *(const float4*)(m + i), b = *(const float4*)(s + i);
    *(float4*)(g_cmask + i) = make_float4(a.x + b.x, a.y + b.y, a.z + b.z, a.w + b.w);
}
__global__ void prep_rpb_kernel(const int* __restrict__ rpi, const float* __restrict__ bt) {
    int i = blockIdx.x * 256 + threadIdx.x;
    int t = rpi[i];
#pragma unroll
    for (int h = 0; h < HEADS; ++h) g_rpb[h * NTOK * NTOK + i] = bt[t * HEADS + h];
}
__global__ void conv_w_kernel(const float* __restrict__ w, int n, int which) {
    int i = blockIdx.x * 256 + threadIdx.x;
    if (i >= n) return;
    int row = i >> 4, c0 = (i & 15) * 8;
    const float* wr = w + row * DIM + c0;
    float4 v0 = *(const float4*)(wr), v1 = *(const float4*)(wr + 4);
    uint4 hv = make_uint4(pk2(v0.x, v0.y), pk2(v0.z, v0.w), pk2(v1.x, v1.y), pk2(v1.z, v1.w));
    uint4 lv = make_uint4(pk2(v0.x - bfh(v0.x), v0.y - bfh(v0.y)),
                          pk2(v0.z - bfh(v0.z), v0.w - bfh(v0.w)),
                          pk2(v1.x - bfh(v1.x), v1.y - bfh(v1.y)),
                          pk2(v1.z - bfh(v1.z), v1.w - bfh(v1.w)));
    if (which == 0) { g_wqkv_h[i] = hv; g_wqkv_l[i] = lv; }
    else            { g_wproj_h[i] = hv; g_wproj_l[i] = lv; }
}

// ---------- dense GEMM (qkv / proj), unchanged from R4 ----------
__device__ __forceinline__ void conv_A(const float* __restrict__ src, uint32_t XH, int tid) {
    for (int i = tid; i < 4096; i += 256) {
        int t = i >> 5, c = (i & 31) * 4;
        float4 v = *(const float4*)(src + t * DIM + c);
        uint32_t o = XH + (uint32_t)(t * PAD + c) * 2u;
        asm volatile("st.shared.v2.b32 [%0], {%1, %2};"
                     :: "r"(o), "r"(pk2(v.x, v.y)), "r"(pk2(v.z, v.w)));
        asm volatile("st.shared.v2.b32 [%0], {%1, %2};"
                     :: "r"(o + SM_XL), "r"(pk2(v.x - bfh(v.x), v.y - bfh(v.y))),
                        "r"(pk2(v.z - bfh(v.z), v.w - bfh(v.w))));
    }
}
__device__ __forceinline__ void cp_W(const uint4* gh, const uint4* gl, uint32_t WH, int tid) {
    for (int i = tid; i < 1024; i += 256) {
        int row = i >> 4, c0 = (i & 15) * 8;
        uint32_t o = WH + (uint32_t)(row * PAD + c0) * 2u;
        uint4 a = __ldg(gh + i), c = __ldg(gl + i);
        asm volatile("st.shared.v4.b32 [%0], {%1,%2,%3,%4};"
                     :: "r"(o), "r"(a.x), "r"(a.y), "r"(a.z), "r"(a.w));
        asm volatile("st.shared.v4.b32 [%0], {%1,%2,%3,%4};"
                     :: "r"(o + (SM_WL - SM_WH)), "r"(c.x), "r"(c.y), "r"(c.z), "r"(c.w));
    }
}
template <int NCHUNK, int MODE>
__device__ __forceinline__ void gemm_mma(const float* __restrict__ xsrc,
                                         const uint4* __restrict__ wh,
                                         const uint4* __restrict__ wl,
                                         const float* __restrict__ bias,
                                         float* __restrict__ gen_out, int b) {
    extern __shared__ unsigned char sraw[];
    uint32_t XH = smem_u32(sraw);
    uint32_t WH = XH + SM_WH;
    int tid = threadIdx.x, wid = tid >> 5, lane = tid & 31;
    conv_A(xsrc, XH, tid);
    int r0 = wid * 16;
    int lr = lane & 15, kh = (lane >> 4) & 1;
    int bl8 = lane & 7, bseg = (lane >> 3) & 1;
    uint32_t abase = XH + (uint32_t)((r0 + lr) * PAD + kh * 8) * 2u;
    uint32_t bbase = WH + (uint32_t)(bl8 * PAD + bseg * 8) * 2u;

    for (int ch = 0; ch < NCHUNK; ++ch) {
        __syncthreads();
        cp_W(wh + ch * 1024, wl + ch * 1024, WH, tid);
        __syncthreads();
        float acc[8][4];
#pragma unroll
        for (int nt = 0; nt < 8; ++nt)
#pragma unroll
            for (int j = 0; j < 4; ++j) acc[nt][j] = 0.f;
#pragma unroll
        for (int k = 0; k < 8; ++k) {
            uint32_t ah[4], al[4];
            uint32_t aa = abase + (uint32_t)(k * 32);
            LDM4(ah, aa);
            LDM4(al, aa + SM_XL);
#pragma unroll
            for (int nt = 0; nt < 8; ++nt) {
                uint32_t ba = bbase + (uint32_t)(nt * 8 * PAD * 2 + k * 32);
                uint32_t bh0, bh1, bl0, bl1;
                LDM2(bh0, bh1, ba);
                LDM2(bl0, bl1, ba + (SM_WL - SM_WH));
                MMA(acc[nt], ah, bh0, bh1);
                MMA(acc[nt], ah, bl0, bl1);
                MMA(acc[nt], al, bh0, bh1);
            }
        }
        int t0 = r0 + (lane >> 2);
#pragma unroll
        for (int nt = 0; nt < 8; ++nt) {
            int f = ch * 64 + nt * 8 + (lane & 3) * 2;
            float bx = __ldg(bias + f), by = __ldg(bias + f + 1);
            if (MODE == 0) {
                int s = f >> 7, h = (f >> 5) & 3, d = f & 31;
                float sc = (s == 0) ? SCALEF : 1.0f;
                float* dst = (s == 0 ? g_q : s == 1 ? g_k : g_v)
                           + ((size_t)b * HEADS + h) * NTOK * HD + d;
                *(float2*)(dst + (size_t)t0 * HD) =
                    make_float2((acc[nt][0] + bx) * sc, (acc[nt][1] + by) * sc);
                *(float2*)(dst + (size_t)(t0 + 8) * HD) =
                    make_float2((acc[nt][2] + bx) * sc, (acc[nt][3] + by) * sc);
            } else {
                *(float2*)(gen_out + ((size_t)b * NTOK + t0) * DIM + f) =
                    make_float2(acc[nt][0] + bx, acc[nt][1] + by);
                *(float2*)(gen_out + ((size_t)b * NTOK + t0 + 8) * DIM + f) =
                    make_float2(acc[nt][2] + bx, acc[nt][3] + by);
            }
        }
    }
}
__global__ __launch_bounds__(256, 2)
void qkv_mma_kernel(const float* __restrict__ x, const float* __restrict__ b_qkv) {
    gemm_mma<6, 0>(x + (size_t)blockIdx.x * NTOK * DIM, g_wqkv_h, g_wqkv_l, b_qkv,
                   nullptr, blockIdx.x);
}
__global__ __launch_bounds__(256, 2)
void proj_mma_kernel(const float* __restrict__ b_proj, float* __restrict__ out) {
    gemm_mma<2, 1>(g_ctx + (size_t)blockIdx.x * NTOK * DIM, g_wproj_h, g_wproj_l, b_proj,
                   out, blockIdx.x);
}

// ---------- attention via mma.sync ----------
// smem (bf16): QH[128][40] QL KH[128][40] KL VTH[32][136] VTL
#define A_QH 0u
#define A_QL 10240u
#define A_KH 20480u
#define A_KL 30720u
#define A_VH 40960u
#define A_VL 49664u
#define ATT_SMEM 58368

__global__ __launch_bounds__(256, 2)
void att_mma_kernel() {
    int b = blockIdx.x, h = blockIdx.y;
    extern __shared__ unsigned char sraw[];
    uint32_t sb = smem_u32(sraw);
    __nv_bfloat16* smb = (__nv_bfloat16*)sraw;

    int tid = threadIdx.x, lane = tid & 31, wid = tid >> 5;
    const float* gq = g_q + ((size_t)b * HEADS + h) * NTOK * HD;
    const float* gk = g_k + ((size_t)b * HEADS + h) * NTOK * HD;
    const float* gv = g_v + ((size_t)b * HEADS + h) * NTOK * HD;

    // fill smem: Q,K row-major [t][d] stride 40; V transposed [d][t] stride 136
    for (int i = tid; i < 1024; i += 256) {
        int t = i >> 3, d = (i & 7) * 4;
        float4 q = *(const float4*)(gq + t * HD + d);
        uint32_t o = (uint32_t)(t * 40 + d) * 2u;
        *(uint2*)((char*)smb + A_QH + o) = make_uint2(pk2(q.x, q.y), pk2(q.z, q.w));
        *(uint2*)((char*)smb + A_QL + o) =
            make_uint2(pk2(q.x - bfh(q.x), q.y - bfh(q.y)), pk2(q.z - bfh(q.z), q.w - bfh(q.w)));
        float4 k = *(const float4*)(gk + t * HD + d);
        *(uint2*)((char*)smb + A_KH + o) = make_uint2(pk2(k.x, k.y), pk2(k.z, k.w));
        *(uint2*)((char*)smb + A_KL + o) =
            make_uint2(pk2(k.x - bfh(k.x), k.y - bfh(k.y)), pk2(k.z - bfh(k.z), k.w - bfh(k.w)));
        float4 v = *(const float4*)(gv + t * HD + d);
        float vv[4] = {v.x, v.y, v.z, v.w};
#pragma unroll
        for (int e = 0; e < 4; ++e) {
            float hi = bfh(vv[e]);
            ((__nv_bfloat16*)((char*)smb + A_VH))[(d + e) * PAD + t] = __float2bfloat16(vv[e]);
            ((__nv_bfloat16*)((char*)smb + A_VL))[(d + e) * PAD + t] = __float2bfloat16(vv[e] - hi);
        }
    }
    __syncthreads();

    int r0 = wid * 16;
    int lr = lane & 15, khf = (lane >> 4) & 1;
    int bl8 = lane & 7, bseg = (lane >> 3) & 1;
    uint32_t qa = sb + A_QH + (uint32_t)((r0 + lr) * 40 + khf * 8) * 2u;
    uint32_t ka = sb + A_KH + (uint32_t)(bl8 * 40 + bseg * 8) * 2u;
    uint32_t va = sb + A_VH + (uint32_t)(bl8 * PAD + bseg * 8) * 2u;

    // ---- S = q k^T (hi/lo 3-term), 16 n-tiles x 2 k-steps ----
    float sacc[16][4];
#pragma unroll
    for (int j = 0; j < 16; ++j)
#pragma unroll
        for (int c = 0; c < 4; ++c) sacc[j][c] = 0.f;
#pragma unroll
    for (int k = 0; k < 2; ++k) {
        uint32_t ah[4], al[4];
        LDM4(ah, qa + k * 32);
        LDM4(al, qa + (A_QL - A_QH) + k * 32);
#pragma unroll
        for (int j = 0; j < 16; ++j) {
            uint32_t ba = ka + (uint32_t)(j * 640 + k * 32);   // 8 rows * 80B
            uint32_t bh0, bh1, bl0, bl1;
            LDM2(bh0, bh1, ba);
            LDM2(bl0, bl1, ba + (A_KL - A_KH));
            MMA(sacc[j], ah, bh0, bh1);
            MMA(sacc[j], ah, bl0, bl1);
            MMA(sacc[j], al, bh0, bh1);
        }
    }

    // ---- add biases at fragment coords ----
    int g = lane >> 2, q2 = (lane & 3) * 2;
    int row0 = r0 + g;
    const float* cm = g_cmask + (size_t)(b & (NMASK - 1)) * NTOK * NTOK + row0 * NTOK + q2;
    const float* rp = g_rpb + (size_t)h * NTOK * NTOK + row0 * NTOK + q2;
#pragma unroll
    for (int j = 0; j < 16; ++j) {
        float2 c0 = *(const float2*)(cm + j * 8);
        float2 p0 = *(const float2*)(rp + j * 8);
        float2 c1 = *(const float2*)(cm + 8 * NTOK + j * 8);
        float2 p1 = *(const float2*)(rp + 8 * NTOK + j * 8);
        sacc[j][0] += c0.x + p0.x;  sacc[j][1] += c0.y + p0.y;
        sacc[j][2] += c1.x + p1.x;  sacc[j][3] += c1.y + p1.y;
    }

    // ---- softmax over the 128 cols (within-thread + quad shfl) ----
    float mx0 = -1e30f, mx1 = -1e30f;
#pragma unroll
    for (int j = 0; j < 16; ++j) {
        mx0 = fmaxf(mx0, fmaxf(sacc[j][0], sacc[j][1]));
        mx1 = fmaxf(mx1, fmaxf(sacc[j][2], sacc[j][3]));
    }
    mx0 = fmaxf(mx0, __shfl_xor_sync(0xffffffffu, mx0, 1));
    mx0 = fmaxf(mx0, __shfl_xor_sync(0xffffffffu, mx0, 2));
    mx1 = fmaxf(mx1, __shfl_xor_sync(0xffffffffu, mx1, 1));
    mx1 = fmaxf(mx1, __shfl_xor_sync(0xffffffffu, mx1, 2));
    float s0 = 0.f, s1 = 0.f;
#pragma unroll
    for (int j = 0; j < 16; ++j) {
        sacc[j][0] = __expf(sacc[j][0] - mx0);
        sacc[j][1] = __expf(sacc[j][1] - mx0);
        sacc[j][2] = __expf(sacc[j][2] - mx1);
        sacc[j][3] = __expf(sacc[j][3] - mx1);
        s0 += sacc[j][0] + sacc[j][1];
        s1 += sacc[j][2] + sacc[j][3];
    }
    s0 += __shfl_xor_sync(0xffffffffu, s0, 1);
    s0 += __shfl_xor_sync(0xffffffffu, s0, 2);
    s1 += __shfl_xor_sync(0xffffffffu, s1, 1);
    s1 += __shfl_xor_sync(0xffffffffu, s1, 2);
    float inv0 = 1.0f / s0, inv1 = 1.0f / s1;

    // ---- PV: P fragments repacked in-register as A operands (hi + lo) ----
    float oacc[4][4];
#pragma unroll
    for (int dn = 0; dn < 4; ++dn)
#pragma unroll
        for (int c = 0; c < 4; ++c) oacc[dn][c] = 0.f;

#pragma unroll
    for (int kk = 0; kk < 8; ++kk) {
        float p00 = sacc[2 * kk][0],     p01 = sacc[2 * kk][1];
        float p10 = sacc[2 * kk][2],     p11 = sacc[2 * kk][3];
        float p20 = sacc[2 * kk + 1][0], p21 = sacc[2 * kk + 1][1];
        float p30 = sacc[2 * kk + 1][2], p31 = sacc[2 * kk + 1][3];
        uint32_t aH[4], aL[4];
        aH[0] = pk2(p00, p01); aH[1] = pk2(p10, p11);
        aH[2] = pk2(p20, p21); aH[3] = pk2(p30, p31);
        aL[0] = pk2(p00 - bfh(p00), p01 - bfh(p01));
        aL[1] = pk2(p10 - bfh(p10), p11 - bfh(p11));
        aL[2] = pk2(p20 - bfh(p20), p21 - bfh(p21));
        aL[3] = pk2(p30 - bfh(p30), p31 - bfh(p31));
#pragma unroll
        for (int dn = 0; dn < 4; ++dn) {
            uint32_t ba = va + (uint32_t)(dn * 8 * PAD * 2 + kk * 32);
            uint32_t bh0, bh1, bl0, bl1;
            LDM2(bh0, bh1, ba);
            LDM2(bl0, bl1, ba + (A_VL - A_VH));
            MMA(oacc[dn], aH, bh0, bh1);
            MMA(oacc[dn], aH, bl0, bl1);
            MMA(oacc[dn], aL, bh0, bh1);
        }
    }

    // ---- write ctx (normalize here) ----
    float* go = g_ctx + ((size_t)b * NTOK + row0) * DIM + h * HD + q2;
#pragma unroll
    for (int dn = 0; dn < 4; ++dn) {
        *(float2*)(go + dn * 8) = make_float2(oacc[dn][0] * inv0, oacc[dn][1] * inv0);
        *(float2*)(go + 8 * DIM + dn * 8) = make_float2(oacc[dn][2] * inv1, oacc[dn][3] * inv1);
    }
}

// ---------- launch ----------
extern "C" void kernel_launch(void* const* d_in, const int* in_sizes, int n_in,
                              void* d_out, int out_size) {
    const float* x          = (const float*)d_in[0];
    const int*   rpi        = (const int*)d_in[1];
    const float* mask       = (const float*)d_in[2];
    const float* sp_mask    = (const float*)d_in[3];
    const float* w_qkv      = (const float*)d_in[4];
    const float* b_qkv      = (const float*)d_in[5];
    const float* bias_table = (const float*)d_in[6];
    const float* w_proj     = (const float*)d_in[7];
    const float* b_proj     = (const float*)d_in[8];
    float* out = (float*)d_out;

    cudaFuncSetAttribute((const void*)qkv_mma_kernel,
                         cudaFuncAttributeMaxDynamicSharedMemorySize, MMA_SMEM);
    cudaFuncSetAttribute((const void*)proj_mma_kernel,
                         cudaFuncAttributeMaxDynamicSharedMemorySize, MMA_SMEM);
    cudaFuncSetAttribute((const void*)att_mma_kernel,
                         cudaFuncAttributeMaxDynamicSharedMemorySize, ATT_SMEM);

    prep_cmask_kernel<<<4096, 256>>>(mask, sp_mask);
    prep_rpb_kernel<<<64, 256>>>(rpi, bias_table);
    conv_w_kernel<<<24, 256>>>(w_qkv, 6144, 0);
    conv_w_kernel<<<8, 256>>>(w_proj, 2048, 1);
    qkv_mma_kernel<<<BWIN, 256, MMA_SMEM>>>(x, b_qkv);
    att_mma_kernel<<<dim3(BWIN, HEADS), 256, ATT_SMEM>>>();
    proj_mma_kernel<<<BWIN, 256, MMA_SMEM>>>(b_proj, out);
}

// round 6
// speedup vs baseline: 2.4745x; 1.0727x over previous
#include <cuda_runtime.h>
#include <cuda_bf16.h>
#include <stdint.h>

#define DIM   128
#define HEADS 4
#define HD    32
#define NTOK  128
#define BWIN  2048
#define NMASK 256
#define SCALEF 0.1767766952966369f
#define PAD   136

__device__ float g_cmask[NMASK * NTOK * NTOK];
__device__ float g_rpb[HEADS * NTOK * NTOK];
__device__ float g_q[(size_t)BWIN * HEADS * NTOK * HD];
__device__ float g_k[(size_t)BWIN * HEADS * NTOK * HD];
__device__ float g_v[(size_t)BWIN * HEADS * NTOK * HD];
__device__ float g_ctx[(size_t)BWIN * NTOK * DIM];
__device__ uint4 g_wqkv_h[6144], g_wqkv_l[6144];
__device__ uint4 g_wproj_h[2048], g_wproj_l[2048];

// ---------- helpers ----------
__device__ __forceinline__ uint32_t smem_u32(const void* p) {
    uint32_t a;
    asm("{ .reg .u64 t; cvta.to.shared.u64 t, %1; cvt.u32.u64 %0, t; }" : "=r"(a) : "l"(p));
    return a;
}
__device__ __forceinline__ uint32_t pk2(float a, float b) {
    __nv_bfloat162 t = __floats2bfloat162_rn(a, b);
    return *reinterpret_cast<uint32_t*>(&t);
}
__device__ __forceinline__ float bfh(float x) {
    return __bfloat162float(__float2bfloat16(x));
}
#define LDM4(r, addr) \
    asm volatile("ldmatrix.sync.aligned.m8n8.x4.shared.b16 {%0,%1,%2,%3}, [%4];" \
                 : "=r"((r)[0]), "=r"((r)[1]), "=r"((r)[2]), "=r"((r)[3]) : "r"(addr))
#define MMA(d, a, b0, b1) \
    asm volatile("mma.sync.aligned.m16n8k16.row.col.f32.bf16.bf16.f32 " \
                 "{%0,%1,%2,%3}, {%4,%5,%6,%7}, {%8,%9}, {%0,%1,%2,%3};" \
                 : "+f"((d)[0]), "+f"((d)[1]), "+f"((d)[2]), "+f"((d)[3]) \
                 : "r"((a)[0]), "r"((a)[1]), "r"((a)[2]), "r"((a)[3]), "r"(b0), "r"(b1))

#define SM_XL 34816
#define SM_WH 69632
#define SM_WL 87040
#define MMA_SMEM 104448

// ---------- prep ----------
__global__ void prep_cmask_kernel(const float* __restrict__ m, const float* __restrict__ s) {
    int i = (blockIdx.x * 256 + threadIdx.x) * 4;
    float4 a = *(const float4*)(m + i), b = *(const float4*)(s + i);
    *(float4*)(g_cmask + i) = make_float4(a.x + b.x, a.y + b.y, a.z + b.z, a.w + b.w);
}
__global__ void prep_rpb_kernel(const int* __restrict__ rpi, const float* __restrict__ bt) {
    int i = blockIdx.x * 256 + threadIdx.x;
    int t = rpi[i];
#pragma unroll
    for (int h = 0; h < HEADS; ++h) g_rpb[h * NTOK * NTOK + i] = bt[t * HEADS + h];
}
__global__ void conv_w_kernel(const float* __restrict__ w, int n, int which) {
    int i = blockIdx.x * 256 + threadIdx.x;
    if (i >= n) return;
    int row = i >> 4, c0 = (i & 15) * 8;
    const float* wr = w + row * DIM + c0;
    float4 v0 = *(const float4*)(wr), v1 = *(const float4*)(wr + 4);
    uint4 hv = make_uint4(pk2(v0.x, v0.y), pk2(v0.z, v0.w), pk2(v1.x, v1.y), pk2(v1.z, v1.w));
    uint4 lv = make_uint4(pk2(v0.x - bfh(v0.x), v0.y - bfh(v0.y)),
                          pk2(v0.z - bfh(v0.z), v0.w - bfh(v0.w)),
                          pk2(v1.x - bfh(v1.x), v1.y - bfh(v1.y)),
                          pk2(v1.z - bfh(v1.z), v1.w - bfh(v1.w)));
    if (which == 0) { g_wqkv_h[i] = hv; g_wqkv_l[i] = lv; }
    else            { g_wproj_h[i] = hv; g_wproj_l[i] = lv; }
}

// ---------- dense GEMM (qkv / proj) ----------
__device__ __forceinline__ void conv_A(const float* __restrict__ src, uint32_t XH, int tid) {
    for (int i = tid; i < 4096; i += 256) {
        int t = i >> 5, c = (i & 31) * 4;
        float4 v = *(const float4*)(src + t * DIM + c);
        uint32_t o = XH + (uint32_t)(t * PAD + c) * 2u;
        asm volatile("st.shared.v2.b32 [%0], {%1, %2};"
                     :: "r"(o), "r"(pk2(v.x, v.y)), "r"(pk2(v.z, v.w)));
        asm volatile("st.shared.v2.b32 [%0], {%1, %2};"
                     :: "r"(o + SM_XL), "r"(pk2(v.x - bfh(v.x), v.y - bfh(v.y))),
                        "r"(pk2(v.z - bfh(v.z), v.w - bfh(v.w))));
    }
}
__device__ __forceinline__ void cp_W(const uint4* gh, const uint4* gl, uint32_t WH, int tid) {
    for (int i = tid; i < 1024; i += 256) {
        int row = i >> 4, c0 = (i & 15) * 8;
        uint32_t o = WH + (uint32_t)(row * PAD + c0) * 2u;
        uint4 a = __ldg(gh + i), c = __ldg(gl + i);
        asm volatile("st.shared.v4.b32 [%0], {%1,%2,%3,%4};"
                     :: "r"(o), "r"(a.x), "r"(a.y), "r"(a.z), "r"(a.w));
        asm volatile("st.shared.v4.b32 [%0], {%1,%2,%3,%4};"
                     :: "r"(o + (SM_WL - SM_WH)), "r"(c.x), "r"(c.y), "r"(c.z), "r"(c.w));
    }
}

// MODE 0: qkv epilogue; MODE 1: generic out + bias
template <int NCHUNK, int MODE>
__device__ __forceinline__ void gemm_mma(const float* __restrict__ xsrc,
                                         const uint4* __restrict__ wh,
                                         const uint4* __restrict__ wl,
                                         const float* __restrict__ bias,
                                         float* __restrict__ gen_out, int b) {
    extern __shared__ unsigned char sraw[];
    uint32_t XH = smem_u32(sraw);
    uint32_t WH = XH + SM_WH;
    int tid = threadIdx.x, wid = tid >> 5, lane = tid & 31;
    conv_A(xsrc, XH, tid);
    __syncthreads();

    int r0 = wid * 16;
    int lr = lane & 15, kh = (lane >> 4) & 1;
    // B x4 pairing: lanes 0-7/8-15 -> n-tile nt (ksegs 0/1); lanes 16-31 -> nt+1
    int brow = ((lane >> 4) & 1) * 8 + (lane & 7);
    int bseg = (lane >> 3) & 1;
    uint32_t abase = XH + (uint32_t)((r0 + lr) * PAD + kh * 8) * 2u;
    uint32_t bbase = WH + (uint32_t)(brow * PAD + bseg * 8) * 2u;

    // A fragments live in registers across all N-chunks
    uint32_t ah[8][4], al[8][4];
#pragma unroll
    for (int k = 0; k < 8; ++k) {
        LDM4(ah[k], abase + (uint32_t)(k * 32));
        LDM4(al[k], abase + SM_XL + (uint32_t)(k * 32));
    }

    for (int ch = 0; ch < NCHUNK; ++ch) {
        __syncthreads();
        cp_W(wh + ch * 1024, wl + ch * 1024, WH, tid);
        __syncthreads();
        float acc[8][4];
#pragma unroll
        for (int nt = 0; nt < 8; ++nt)
#pragma unroll
            for (int j = 0; j < 4; ++j) acc[nt][j] = 0.f;
#pragma unroll
        for (int k = 0; k < 8; ++k) {
#pragma unroll
            for (int ntp = 0; ntp < 4; ++ntp) {
                uint32_t ba = bbase + (uint32_t)(ntp * 16 * PAD * 2 + k * 32);
                uint32_t bh[4], bl[4];
                LDM4(bh, ba);
                LDM4(bl, ba + (SM_WL - SM_WH));
                MMA(acc[2 * ntp],     ah[k], bh[0], bh[1]);
                MMA(acc[2 * ntp],     ah[k], bl[0], bl[1]);
                MMA(acc[2 * ntp],     al[k], bh[0], bh[1]);
                MMA(acc[2 * ntp + 1], ah[k], bh[2], bh[3]);
                MMA(acc[2 * ntp + 1], ah[k], bl[2], bl[3]);
                MMA(acc[2 * ntp + 1], al[k], bh[2], bh[3]);
            }
        }
        int t0 = r0 + (lane >> 2);
#pragma unroll
        for (int nt = 0; nt < 8; ++nt) {
            int f = ch * 64 + nt * 8 + (lane & 3) * 2;
            float bx = __ldg(bias + f), by = __ldg(bias + f + 1);
            if (MODE == 0) {
                int s = f >> 7, h = (f >> 5) & 3, d = f & 31;
                float sc = (s == 0) ? SCALEF : 1.0f;
                float* dst = (s == 0 ? g_q : s == 1 ? g_k : g_v)
                           + ((size_t)b * HEADS + h) * NTOK * HD + d;
                *(float2*)(dst + (size_t)t0 * HD) =
                    make_float2((acc[nt][0] + bx) * sc, (acc[nt][1] + by) * sc);
                *(float2*)(dst + (size_t)(t0 + 8) * HD) =
                    make_float2((acc[nt][2] + bx) * sc, (acc[nt][3] + by) * sc);
            } else {
                *(float2*)(gen_out + ((size_t)b * NTOK + t0) * DIM + f) =
                    make_float2(acc[nt][0] + bx, acc[nt][1] + by);
                *(float2*)(gen_out + ((size_t)b * NTOK + t0 + 8) * DIM + f) =
                    make_float2(acc[nt][2] + bx, acc[nt][3] + by);
            }
        }
    }
}
__global__ __launch_bounds__(256, 2)
void qkv_mma_kernel(const float* __restrict__ x, const float* __restrict__ b_qkv) {
    gemm_mma<6, 0>(x + (size_t)blockIdx.x * NTOK * DIM, g_wqkv_h, g_wqkv_l, b_qkv,
                   nullptr, blockIdx.x);
}
__global__ __launch_bounds__(256, 2)
void proj_mma_kernel(const float* __restrict__ b_proj, float* __restrict__ out) {
    gemm_mma<2, 1>(g_ctx + (size_t)blockIdx.x * NTOK * DIM, g_wproj_h, g_wproj_l, b_proj,
                   out, blockIdx.x);
}

// ---------- attention via mma.sync ----------
#define A_QH 0u
#define A_QL 10240u
#define A_KH 20480u
#define A_KL 30720u
#define A_VH 40960u
#define A_VL 49664u
#define ATT_SMEM 58368

__global__ __launch_bounds__(256, 2)
void att_mma_kernel() {
    int b = blockIdx.x, h = blockIdx.y;
    extern __shared__ unsigned char sraw[];
    uint32_t sb = smem_u32(sraw);
    __nv_bfloat16* smb = (__nv_bfloat16*)sraw;

    int tid = threadIdx.x, lane = tid & 31, wid = tid >> 5;
    const float* gq = g_q + ((size_t)b * HEADS + h) * NTOK * HD;
    const float* gk = g_k + ((size_t)b * HEADS + h) * NTOK * HD;
    const float* gv = g_v + ((size_t)b * HEADS + h) * NTOK * HD;

    for (int i = tid; i < 1024; i += 256) {
        int t = i >> 3, d = (i & 7) * 4;
        float4 q = *(const float4*)(gq + t * HD + d);
        uint32_t o = (uint32_t)(t * 40 + d) * 2u;
        *(uint2*)((char*)smb + A_QH + o) = make_uint2(pk2(q.x, q.y), pk2(q.z, q.w));
        *(uint2*)((char*)smb + A_QL + o) =
            make_uint2(pk2(q.x - bfh(q.x), q.y - bfh(q.y)), pk2(q.z - bfh(q.z), q.w - bfh(q.w)));
        float4 k = *(const float4*)(gk + t * HD + d);
        *(uint2*)((char*)smb + A_KH + o) = make_uint2(pk2(k.x, k.y), pk2(k.z, k.w));
        *(uint2*)((char*)smb + A_KL + o) =
            make_uint2(pk2(k.x - bfh(k.x), k.y - bfh(k.y)), pk2(k.z - bfh(k.z), k.w - bfh(k.w)));
        float4 v = *(const float4*)(gv + t * HD + d);
        float vv[4] = {v.x, v.y, v.z, v.w};
#pragma unroll
        for (int e = 0; e < 4; ++e) {
            float hi = bfh(vv[e]);
            ((__nv_bfloat16*)((char*)smb + A_VH))[(d + e) * PAD + t] = __float2bfloat16(vv[e]);
            ((__nv_bfloat16*)((char*)smb + A_VL))[(d + e) * PAD + t] = __float2bfloat16(vv[e] - hi);
        }
    }
    __syncthreads();

    int r0 = wid * 16;
    int lr = lane & 15, khf = (lane >> 4) & 1;
    int brow = ((lane >> 4) & 1) * 8 + (lane & 7);
    int bseg = (lane >> 3) & 1;
    uint32_t qa = sb + A_QH + (uint32_t)((r0 + lr) * 40 + khf * 8) * 2u;
    uint32_t ka = sb + A_KH + (uint32_t)(brow * 40 + bseg * 8) * 2u;
    uint32_t va = sb + A_VH + (uint32_t)(brow * PAD + bseg * 8) * 2u;

    // A fragments (Q) in regs
    uint32_t ah[2][4], al[2][4];
#pragma unroll
    for (int k = 0; k < 2; ++k) {
        LDM4(ah[k], qa + (uint32_t)(k * 32));
        LDM4(al[k], qa + (A_QL - A_QH) + (uint32_t)(k * 32));
    }

    // ---- S = q k^T, paired n-tiles ----
    float sacc[16][4];
#pragma unroll
    for (int j = 0; j < 16; ++j)
#pragma unroll
        for (int c = 0; c < 4; ++c) sacc[j][c] = 0.f;
#pragma unroll
    for (int ntp = 0; ntp < 8; ++ntp) {
#pragma unroll
        for (int k = 0; k < 2; ++k) {
            uint32_t ba = ka + (uint32_t)(ntp * 16 * 40 * 2 + k * 32);
            uint32_t bh[4], bl[4];
            LDM4(bh, ba);
            LDM4(bl, ba + (A_KL - A_KH));
            MMA(sacc[2 * ntp],     ah[k], bh[0], bh[1]);
            MMA(sacc[2 * ntp],     ah[k], bl[0], bl[1]);
            MMA(sacc[2 * ntp],     al[k], bh[0], bh[1]);
            MMA(sacc[2 * ntp + 1], ah[k], bh[2], bh[3]);
            MMA(sacc[2 * ntp + 1], ah[k], bl[2], bl[3]);
            MMA(sacc[2 * ntp + 1], al[k], bh[2], bh[3]);
        }
    }

    // ---- add biases ----
    int g = lane >> 2, q2 = (lane & 3) * 2;
    int row0 = r0 + g;
    const float* cm = g_cmask + (size_t)(b & (NMASK - 1)) * NTOK * NTOK + row0 * NTOK + q2;
    const float* rp = g_rpb + (size_t)h * NTOK * NTOK + row0 * NTOK + q2;
#pragma unroll
    for (int j = 0; j < 16; ++j) {
        float2 c0 = *(const float2*)(cm + j * 8);
        float2 p0 = *(const float2*)(rp + j * 8);
        float2 c1 = *(const float2*)(cm + 8 * NTOK + j * 8);
        float2 p1 = *(const float2*)(rp + 8 * NTOK + j * 8);
        sacc[j][0] += c0.x + p0.x;  sacc[j][1] += c0.y + p0.y;
        sacc[j][2] += c1.x + p1.x;  sacc[j][3] += c1.y + p1.y;
    }

    // ---- softmax ----
    float mx0 = -1e30f, mx1 = -1e30f;
#pragma unroll
    for (int j = 0; j < 16; ++j) {
        mx0 = fmaxf(mx0, fmaxf(sacc[j][0], sacc[j][1]));
        mx1 = fmaxf(mx1, fmaxf(sacc[j][2], sacc[j][3]));
    }
    mx0 = fmaxf(mx0, __shfl_xor_sync(0xffffffffu, mx0, 1));
    mx0 = fmaxf(mx0, __shfl_xor_sync(0xffffffffu, mx0, 2));
    mx1 = fmaxf(mx1, __shfl_xor_sync(0xffffffffu, mx1, 1));
    mx1 = fmaxf(mx1, __shfl_xor_sync(0xffffffffu, mx1, 2));
    float s0 = 0.f, s1 = 0.f;
#pragma unroll
    for (int j = 0; j < 16; ++j) {
        sacc[j][0] = __expf(sacc[j][0] - mx0);
        sacc[j][1] = __expf(sacc[j][1] - mx0);
        sacc[j][2] = __expf(sacc[j][2] - mx1);
        sacc[j][3] = __expf(sacc[j][3] - mx1);
        s0 += sacc[j][0] + sacc[j][1];
        s1 += sacc[j][2] + sacc[j][3];
    }
    s0 += __shfl_xor_sync(0xffffffffu, s0, 1);
    s0 += __shfl_xor_sync(0xffffffffu, s0, 2);
    s1 += __shfl_xor_sync(0xffffffffu, s1, 1);
    s1 += __shfl_xor_sync(0xffffffffu, s1, 2);
    float inv0 = 1.0f / s0, inv1 = 1.0f / s1;

    // ---- PV: P repacked in-register, V n-tiles paired ----
    float oacc[4][4];
#pragma unroll
    for (int dn = 0; dn < 4; ++dn)
#pragma unroll
        for (int c = 0; c < 4; ++c) oacc[dn][c] = 0.f;

#pragma unroll
    for (int kk = 0; kk < 8; ++kk) {
        float p00 = sacc[2 * kk][0],     p01 = sacc[2 * kk][1];
        float p10 = sacc[2 * kk][2],     p11 = sacc[2 * kk][3];
        float p20 = sacc[2 * kk + 1][0], p21 = sacc[2 * kk + 1][1];
        float p30 = sacc[2 * kk + 1][2], p31 = sacc[2 * kk + 1][3];
        uint32_t aH[4], aL[4];
        aH[0] = pk2(p00, p01); aH[1] = pk2(p10, p11);
        aH[2] = pk2(p20, p21); aH[3] = pk2(p30, p31);
        aL[0] = pk2(p00 - bfh(p00), p01 - bfh(p01));
        aL[1] = pk2(p10 - bfh(p10), p11 - bfh(p11));
        aL[2] = pk2(p20 - bfh(p20), p21 - bfh(p21));
        aL[3] = pk2(p30 - bfh(p30), p31 - bfh(p31));
#pragma unroll
        for (int dnp = 0; dnp < 2; ++dnp) {
            uint32_t ba = va + (uint32_t)(dnp * 16 * PAD * 2 + kk * 32);
            uint32_t bh[4], bl[4];
            LDM4(bh, ba);
            LDM4(bl, ba + (A_VL - A_VH));
            MMA(oacc[2 * dnp],     aH, bh[0], bh[1]);
            MMA(oacc[2 * dnp],     aH, bl[0], bl[1]);
            MMA(oacc[2 * dnp],     aL, bh[0], bh[1]);
            MMA(oacc[2 * dnp + 1], aH, bh[2], bh[3]);
            MMA(oacc[2 * dnp + 1], aH, bl[2], bl[3]);
            MMA(oacc[2 * dnp + 1], aL, bh[2], bh[3]);
        }
    }

    float* go = g_ctx + ((size_t)b * NTOK + row0) * DIM + h * HD + q2;
#pragma unroll
    for (int dn = 0; dn < 4; ++dn) {
        *(float2*)(go + dn * 8) = make_float2(oacc[dn][0] * inv0, oacc[dn][1] * inv0);
        *(float2*)(go + 8 * DIM + dn * 8) = make_float2(oacc[dn][2] * inv1, oacc[dn][3] * inv1);
    }
}

// ---------- launch ----------
extern "C" void kernel_launch(void* const* d_in, const int* in_sizes, int n_in,
                              void* d_out, int out_size) {
    const float* x          = (const float*)d_in[0];
    const int*   rpi        = (const int*)d_in[1];
    const float* mask       = (const float*)d_in[2];
    const float* sp_mask    = (const float*)d_in[3];
    const float* w_qkv      = (const float*)d_in[4];
    const float* b_qkv      = (const float*)d_in[5];
    const float* bias_table = (const float*)d_in[6];
    const float* w_proj     = (const float*)d_in[7];
    const float* b_proj     = (const float*)d_in[8];
    float* out = (float*)d_out;

    cudaFuncSetAttribute((const void*)qkv_mma_kernel,
                         cudaFuncAttributeMaxDynamicSharedMemorySize, MMA_SMEM);
    cudaFuncSetAttribute((const void*)proj_mma_kernel,
                         cudaFuncAttributeMaxDynamicSharedMemorySize, MMA_SMEM);
    cudaFuncSetAttribute((const void*)att_mma_kernel,
                         cudaFuncAttributeMaxDynamicSharedMemorySize, ATT_SMEM);

    prep_cmask_kernel<<<4096, 256>>>(mask, sp_mask);
    prep_rpb_kernel<<<64, 256>>>(rpi, bias_table);
    conv_w_kernel<<<24, 256>>>(w_qkv, 6144, 0);
    conv_w_kernel<<<8, 256>>>(w_proj, 2048, 1);
    qkv_mma_kernel<<<BWIN, 256, MMA_SMEM>>>(x, b_qkv);
    att_mma_kernel<<<dim3(BWIN, HEADS), 256, ATT_SMEM>>>();
    proj_mma_kernel<<<BWIN, 256, MMA_SMEM>>>(b_proj, out);
}

// round 7
// speedup vs baseline: 2.6153x; 1.0569x over previous
#include <cuda_runtime.h>
#include <cuda_bf16.h>
#include <stdint.h>

#define DIM   128
#define HEADS 4
#define HD    32
#define NTOK  128
#define BWIN  2048
#define NMASK 256
#define SCALEF 0.1767766952966369f
#define PAD   136

// merged bias: (w,h) plane of mask+sp_mask+rpb
__device__ float g_cmrp[(size_t)NMASK * HEADS * NTOK * NTOK];
// packed bf16 hi/lo interchange: [b,h][t][16 dpairs] -> uint2{hi01, lo01}
__device__ uint2 g_qp[(size_t)BWIN * HEADS * NTOK * 16];
__device__ uint2 g_kp[(size_t)BWIN * HEADS * NTOK * 16];
__device__ uint2 g_vp[(size_t)BWIN * HEADS * NTOK * 16];
// packed ctx: [b][t][64 dpairs]
__device__ uint2 g_ctxp[(size_t)BWIN * NTOK * 64];
__device__ uint4 g_wqkv_h[6144], g_wqkv_l[6144];
__device__ uint4 g_wproj_h[2048], g_wproj_l[2048];

// ---------- helpers ----------
__device__ __forceinline__ uint32_t smem_u32(const void* p) {
    uint32_t a;
    asm("{ .reg .u64 t; cvta.to.shared.u64 t, %1; cvt.u32.u64 %0, t; }" : "=r"(a) : "l"(p));
    return a;
}
__device__ __forceinline__ uint32_t pk2(float a, float b) {
    __nv_bfloat162 t = __floats2bfloat162_rn(a, b);
    return *reinterpret_cast<uint32_t*>(&t);
}
__device__ __forceinline__ float bfh(float x) {
    return __bfloat162float(__float2bfloat16(x));
}
#define LDM4(r, addr) \
    asm volatile("ldmatrix.sync.aligned.m8n8.x4.shared.b16 {%0,%1,%2,%3}, [%4];" \
                 : "=r"((r)[0]), "=r"((r)[1]), "=r"((r)[2]), "=r"((r)[3]) : "r"(addr))
#define LDM4T(r, addr) \
    asm volatile("ldmatrix.sync.aligned.m8n8.x4.trans.shared.b16 {%0,%1,%2,%3}, [%4];" \
                 : "=r"((r)[0]), "=r"((r)[1]), "=r"((r)[2]), "=r"((r)[3]) : "r"(addr))
#define MMA(d, a, b0, b1) \
    asm volatile("mma.sync.aligned.m16n8k16.row.col.f32.bf16.bf16.f32 " \
                 "{%0,%1,%2,%3}, {%4,%5,%6,%7}, {%8,%9}, {%0,%1,%2,%3};" \
                 : "+f"((d)[0]), "+f"((d)[1]), "+f"((d)[2]), "+f"((d)[3]) \
                 : "r"((a)[0]), "r"((a)[1]), "r"((a)[2]), "r"((a)[3]), "r"(b0), "r"(b1))
#define STS2(addr, a, b) \
    asm volatile("st.shared.v2.b32 [%0], {%1, %2};" :: "r"(addr), "r"(a), "r"(b))

#define SM_XL 34816
#define SM_WH 69632
#define SM_WL 87040
#define MMA_SMEM 104448

// ---------- prep ----------
__global__ void prep_cmrp_kernel(const float* __restrict__ m, const float* __restrict__ s,
                                 const int* __restrict__ rpi, const float* __restrict__ bt) {
    int gi = (blockIdx.x * 256 + threadIdx.x) * 4;    // 4096 blocks x 256 thr cover 256*16384
    int w = gi >> 14, i = gi & 16383;
    float4 a = *(const float4*)(m + (size_t)w * 16384 + i);
    float4 c = *(const float4*)(s + (size_t)w * 16384 + i);
    a.x += c.x; a.y += c.y; a.z += c.z; a.w += c.w;
    int4 r = *(const int4*)(rpi + i);
#pragma unroll
    for (int h = 0; h < HEADS; ++h) {
        float4 o = make_float4(a.x + __ldg(bt + r.x * 4 + h), a.y + __ldg(bt + r.y * 4 + h),
                               a.z + __ldg(bt + r.z * 4 + h), a.w + __ldg(bt + r.w * 4 + h));
        *(float4*)(g_cmrp + (((size_t)w * 4 + h) << 14) + i) = o;
    }
}
__global__ void conv_w_kernel(const float* __restrict__ w, int n, int which) {
    int i = blockIdx.x * 256 + threadIdx.x;
    if (i >= n) return;
    int row = i >> 4, c0 = (i & 15) * 8;
    const float* wr = w + row * DIM + c0;
    float4 v0 = *(const float4*)(wr), v1 = *(const float4*)(wr + 4);
    uint4 hv = make_uint4(pk2(v0.x, v0.y), pk2(v0.z, v0.w), pk2(v1.x, v1.y), pk2(v1.z, v1.w));
    uint4 lv = make_uint4(pk2(v0.x - bfh(v0.x), v0.y - bfh(v0.y)),
                          pk2(v0.z - bfh(v0.z), v0.w - bfh(v0.w)),
                          pk2(v1.x - bfh(v1.x), v1.y - bfh(v1.y)),
                          pk2(v1.z - bfh(v1.z), v1.w - bfh(v1.w)));
    if (which == 0) { g_wqkv_h[i] = hv; g_wqkv_l[i] = lv; }
    else            { g_wproj_h[i] = hv; g_wproj_l[i] = lv; }
}

// ---------- dense GEMM (qkv / proj) ----------
__device__ __forceinline__ void conv_A(const float* __restrict__ src, uint32_t XH, int tid) {
    for (int i = tid; i < 4096; i += 256) {
        int t = i >> 5, c = (i & 31) * 4;
        float4 v = *(const float4*)(src + t * DIM + c);
        uint32_t o = XH + (uint32_t)(t * PAD + c) * 2u;
        STS2(o, pk2(v.x, v.y), pk2(v.z, v.w));
        STS2(o + SM_XL, pk2(v.x - bfh(v.x), v.y - bfh(v.y)),
             pk2(v.z - bfh(v.z), v.w - bfh(v.w)));
    }
}
__device__ __forceinline__ void fill_A_packed(const uint4* __restrict__ cp, uint32_t XH, int tid) {
    for (int i = tid; i < 4096; i += 256) {
        int t = i >> 5, p2 = i & 31;
        uint4 v = __ldg(cp + i);
        uint32_t o = XH + (uint32_t)(t * 272 + p2 * 8);
        STS2(o, v.x, v.z);
        STS2(o + SM_XL, v.y, v.w);
    }
}
__device__ __forceinline__ void cp_W(const uint4* gh, const uint4* gl, uint32_t WH, int tid) {
    for (int i = tid; i < 1024; i += 256) {
        int row = i >> 4, c0 = (i & 15) * 8;
        uint32_t o = WH + (uint32_t)(row * PAD + c0) * 2u;
        uint4 a = __ldg(gh + i), c = __ldg(gl + i);
        asm volatile("st.shared.v4.b32 [%0], {%1,%2,%3,%4};"
                     :: "r"(o), "r"(a.x), "r"(a.y), "r"(a.z), "r"(a.w));
        asm volatile("st.shared.v4.b32 [%0], {%1,%2,%3,%4};"
                     :: "r"(o + (SM_WL - SM_WH)), "r"(c.x), "r"(c.y), "r"(c.z), "r"(c.w));
    }
}

// MODE 0: qkv epilogue (packed hi/lo q/k/v); MODE 1: proj (fp32 out + bias)
template <int NCHUNK, int MODE>
__device__ __forceinline__ void gemm_mma(const float* __restrict__ xsrc,
                                         const uint4* __restrict__ wh,
                                         const uint4* __restrict__ wl,
                                         const float* __restrict__ bias,
                                         float* __restrict__ gen_out, int b) {
    extern __shared__ unsigned char sraw[];
    uint32_t XH = smem_u32(sraw);
    uint32_t WH = XH + SM_WH;
    int tid = threadIdx.x, wid = tid >> 5, lane = tid & 31;
    if (MODE == 0) conv_A(xsrc, XH, tid);
    else           fill_A_packed((const uint4*)g_ctxp + (size_t)b * 4096, XH, tid);
    __syncthreads();

    int r0 = wid * 16;
    int lr = lane & 15, kh = (lane >> 4) & 1;
    int brow = ((lane >> 4) & 1) * 8 + (lane & 7);
    int bseg = (lane >> 3) & 1;
    uint32_t abase = XH + (uint32_t)((r0 + lr) * PAD + kh * 8) * 2u;
    uint32_t bbase = WH + (uint32_t)(brow * PAD + bseg * 8) * 2u;

    uint32_t ah[8][4], al[8][4];
#pragma unroll
    for (int k = 0; k < 8; ++k) {
        LDM4(ah[k], abase + (uint32_t)(k * 32));
        LDM4(al[k], abase + SM_XL + (uint32_t)(k * 32));
    }

    for (int ch = 0; ch < NCHUNK; ++ch) {
        __syncthreads();
        cp_W(wh + ch * 1024, wl + ch * 1024, WH, tid);
        __syncthreads();
        float acc[8][4];
#pragma unroll
        for (int nt = 0; nt < 8; ++nt)
#pragma unroll
            for (int j = 0; j < 4; ++j) acc[nt][j] = 0.f;
#pragma unroll
        for (int k = 0; k < 8; ++k) {
#pragma unroll
            for (int ntp = 0; ntp < 4; ++ntp) {
                uint32_t ba = bbase + (uint32_t)(ntp * 16 * PAD * 2 + k * 32);
                uint32_t bh[4], bl[4];
                LDM4(bh, ba);
                LDM4(bl, ba + (SM_WL - SM_WH));
                MMA(acc[2 * ntp],     ah[k], bh[0], bh[1]);
                MMA(acc[2 * ntp],     ah[k], bl[0], bl[1]);
                MMA(acc[2 * ntp],     al[k], bh[0], bh[1]);
                MMA(acc[2 * ntp + 1], ah[k], bh[2], bh[3]);
                MMA(acc[2 * ntp + 1], ah[k], bl[2], bl[3]);
                MMA(acc[2 * ntp + 1], al[k], bh[2], bh[3]);
            }
        }
        int t0 = r0 + (lane >> 2);
#pragma unroll
        for (int nt = 0; nt < 8; ++nt) {
            int f = ch * 64 + nt * 8 + (lane & 3) * 2;
            float bx = __ldg(bias + f), by = __ldg(bias + f + 1);
            if (MODE == 0) {
                int s = f >> 7, h = (f >> 5) & 3, dpair = (f & 31) >> 1;
                float sc = (s == 0) ? SCALEF : 1.0f;
                uint2* plane = (s == 0 ? g_qp : s == 1 ? g_kp : g_vp)
                             + ((size_t)b * HEADS + h) * NTOK * 16 + dpair;
                float v0 = (acc[nt][0] + bx) * sc, v1 = (acc[nt][1] + by) * sc;
                plane[(size_t)t0 * 16] =
                    make_uint2(pk2(v0, v1), pk2(v0 - bfh(v0), v1 - bfh(v1)));
                float v2 = (acc[nt][2] + bx) * sc, v3 = (acc[nt][3] + by) * sc;
                plane[(size_t)(t0 + 8) * 16] =
                    make_uint2(pk2(v2, v3), pk2(v2 - bfh(v2), v3 - bfh(v3)));
            } else {
                *(float2*)(gen_out + ((size_t)b * NTOK + t0) * DIM + f) =
                    make_float2(acc[nt][0] + bx, acc[nt][1] + by);
                *(float2*)(gen_out + ((size_t)b * NTOK + t0 + 8) * DIM + f) =
                    make_float2(acc[nt][2] + bx, acc[nt][3] + by);
            }
        }
    }
}
__global__ __launch_bounds__(256, 2)
void qkv_mma_kernel(const float* __restrict__ x, const float* __restrict__ b_qkv) {
    gemm_mma<6, 0>(x + (size_t)blockIdx.x * NTOK * DIM, g_wqkv_h, g_wqkv_l, b_qkv,
                   nullptr, blockIdx.x);
}
__global__ __launch_bounds__(256, 2)
void proj_mma_kernel(const float* __restrict__ b_proj, float* __restrict__ out) {
    gemm_mma<2, 1>(nullptr, g_wproj_h, g_wproj_l, b_proj, out, blockIdx.x);
}

// ---------- attention ----------
// smem: QH QL KH KL VH VL, each [128 t][40 elems] bf16 = 10240B
#define A_QH 0u
#define A_QL 10240u
#define A_KH 20480u
#define A_KL 30720u
#define A_VH 40960u
#define A_VL 51200u
#define ATT_SMEM 61440

__global__ __launch_bounds__(256, 2)
void att_mma_kernel(float* dummy) {
    int b = blockIdx.x, h = blockIdx.y;
    extern __shared__ unsigned char sraw[];
    uint32_t sb = smem_u32(sraw);

    int tid = threadIdx.x, lane = tid & 31, wid = tid >> 5;
    size_t base = ((size_t)b * HEADS + h) * 1024;   // uint4 units (128t x 8)
    const uint4* qp = (const uint4*)g_qp + base;
    const uint4* kp = (const uint4*)g_kp + base;
    const uint4* vp = (const uint4*)g_vp + base;

    // pure copy/deinterleave fill
    for (int i = tid; i < 1024; i += 256) {
        int t = i >> 3, p2 = i & 7;
        uint32_t o = (uint32_t)(t * 80 + p2 * 8);
        uint4 q = __ldg(qp + i);
        STS2(sb + A_QH + o, q.x, q.z);
        STS2(sb + A_QL + o, q.y, q.w);
        uint4 k = __ldg(kp + i);
        STS2(sb + A_KH + o, k.x, k.z);
        STS2(sb + A_KL + o, k.y, k.w);
        uint4 v = __ldg(vp + i);
        STS2(sb + A_VH + o, v.x, v.z);
        STS2(sb + A_VL + o, v.y, v.w);
    }
    __syncthreads();

    int r0 = wid * 16;
    int lr = lane & 15, khf = (lane >> 4) & 1;
    int brow = ((lane >> 4) & 1) * 8 + (lane & 7);
    int bseg = (lane >> 3) & 1;
    uint32_t qa = sb + A_QH + (uint32_t)((r0 + lr) * 40 + khf * 8) * 2u;
    uint32_t ka = sb + A_KH + (uint32_t)(brow * 40 + bseg * 8) * 2u;
    // trans-ldmatrix lane mapping for V[t][d]:
    int vrow = (lane & 7) + ((lane >> 3) & 1) * 8;
    uint32_t va = sb + A_VH + (uint32_t)(vrow * 80 + ((lane >> 4) & 1) * 16);

    uint32_t ah[2][4], al[2][4];
#pragma unroll
    for (int k = 0; k < 2; ++k) {
        LDM4(ah[k], qa + (uint32_t)(k * 32));
        LDM4(al[k], qa + (A_QL - A_QH) + (uint32_t)(k * 32));
    }

    // ---- S = q k^T ----
    float sacc[16][4];
#pragma unroll
    for (int j = 0; j < 16; ++j)
#pragma unroll
        for (int c = 0; c < 4; ++c) sacc[j][c] = 0.f;
#pragma unroll
    for (int ntp = 0; ntp < 8; ++ntp) {
#pragma unroll
        for (int k = 0; k < 2; ++k) {
            uint32_t ba = ka + (uint32_t)(ntp * 16 * 80 + k * 32);
            uint32_t bh[4], bl[4];
            LDM4(bh, ba);
            LDM4(bl, ba + (A_KL - A_KH));
            MMA(sacc[2 * ntp],     ah[k], bh[0], bh[1]);
            MMA(sacc[2 * ntp],     ah[k], bl[0], bl[1]);
            MMA(sacc[2 * ntp],     al[k], bh[0], bh[1]);
            MMA(sacc[2 * ntp + 1], ah[k], bh[2], bh[3]);
            MMA(sacc[2 * ntp + 1], ah[k], bl[2], bl[3]);
            MMA(sacc[2 * ntp + 1], al[k], bh[2], bh[3]);
        }
    }

    // ---- merged bias (single stream) ----
    int g = lane >> 2, q2 = (lane & 3) * 2;
    int row0 = r0 + g;
    const float* cm = g_cmrp + (((size_t)(b & (NMASK - 1)) * HEADS + h) << 14)
                    + row0 * NTOK + q2;
#pragma unroll
    for (int j = 0; j < 16; ++j) {
        float2 c0 = *(const float2*)(cm + j * 8);
        float2 c1 = *(const float2*)(cm + 8 * NTOK + j * 8);
        sacc[j][0] += c0.x;  sacc[j][1] += c0.y;
        sacc[j][2] += c1.x;  sacc[j][3] += c1.y;
    }

    // ---- softmax ----
    float mx0 = -1e30f, mx1 = -1e30f;
#pragma unroll
    for (int j = 0; j < 16; ++j) {
        mx0 = fmaxf(mx0, fmaxf(sacc[j][0], sacc[j][1]));
        mx1 = fmaxf(mx1, fmaxf(sacc[j][2], sacc[j][3]));
    }
    mx0 = fmaxf(mx0, __shfl_xor_sync(0xffffffffu, mx0, 1));
    mx0 = fmaxf(mx0, __shfl_xor_sync(0xffffffffu, mx0, 2));
    mx1 = fmaxf(mx1, __shfl_xor_sync(0xffffffffu, mx1, 1));
    mx1 = fmaxf(mx1, __shfl_xor_sync(0xffffffffu, mx1, 2));
    float s0 = 0.f, s1 = 0.f;
#pragma unroll
    for (int j = 0; j < 16; ++j) {
        sacc[j][0] = __expf(sacc[j][0] - mx0);
        sacc[j][1] = __expf(sacc[j][1] - mx0);
        sacc[j][2] = __expf(sacc[j][2] - mx1);
        sacc[j][3] = __expf(sacc[j][3] - mx1);
        s0 += sacc[j][0] + sacc[j][1];
        s1 += sacc[j][2] + sacc[j][3];
    }
    s0 += __shfl_xor_sync(0xffffffffu, s0, 1);
    s0 += __shfl_xor_sync(0xffffffffu, s0, 2);
    s1 += __shfl_xor_sync(0xffffffffu, s1, 1);
    s1 += __shfl_xor_sync(0xffffffffu, s1, 2);
    float inv0 = 1.0f / s0, inv1 = 1.0f / s1;

    // ---- PV: P in-register, V via trans-ldmatrix ----
    float oacc[4][4];
#pragma unroll
    for (int dn = 0; dn < 4; ++dn)
#pragma unroll
        for (int c = 0; c < 4; ++c) oacc[dn][c] = 0.f;
#pragma unroll
    for (int kk = 0; kk < 8; ++kk) {
        float p00 = sacc[2 * kk][0],     p01 = sacc[2 * kk][1];
        float p10 = sacc[2 * kk][2],     p11 = sacc[2 * kk][3];
        float p20 = sacc[2 * kk + 1][0], p21 = sacc[2 * kk + 1][1];
        float p30 = sacc[2 * kk + 1][2], p31 = sacc[2 * kk + 1][3];
        uint32_t aH[4], aL[4];
        aH[0] = pk2(p00, p01); aH[1] = pk2(p10, p11);
        aH[2] = pk2(p20, p21); aH[3] = pk2(p30, p31);
        aL[0] = pk2(p00 - bfh(p00), p01 - bfh(p01));
        aL[1] = pk2(p10 - bfh(p10), p11 - bfh(p11));
        aL[2] = pk2(p20 - bfh(p20), p21 - bfh(p21));
        aL[3] = pk2(p30 - bfh(p30), p31 - bfh(p31));
#pragma unroll
        for (int dnp = 0; dnp < 2; ++dnp) {
            uint32_t ba = va + (uint32_t)(kk * 16 * 80 + dnp * 32);
            uint32_t bh[4], bl[4];
            LDM4T(bh, ba);
            LDM4T(bl, ba + (A_VL - A_VH));
            MMA(oacc[2 * dnp],     aH, bh[0], bh[1]);
            MMA(oacc[2 * dnp],     aH, bl[0], bl[1]);
            MMA(oacc[2 * dnp],     aL, bh[0], bh[1]);
            MMA(oacc[2 * dnp + 1], aH, bh[2], bh[3]);
            MMA(oacc[2 * dnp + 1], aH, bl[2], bl[3]);
            MMA(oacc[2 * dnp + 1], aL, bh[2], bh[3]);
        }
    }

    // ---- write ctx packed hi/lo ----
    uint2* cp0 = g_ctxp + ((size_t)b * NTOK + row0) * 64 + h * 16 + (lane & 3);
#pragma unroll
    for (int dn = 0; dn < 4; ++dn) {
        float v0 = oacc[dn][0] * inv0, v1 = oacc[dn][1] * inv0;
        cp0[dn * 4] = make_uint2(pk2(v0, v1), pk2(v0 - bfh(v0), v1 - bfh(v1)));
        float v2 = oacc[dn][2] * inv1, v3 = oacc[dn][3] * inv1;
        cp0[8 * 64 + dn * 4] = make_uint2(pk2(v2, v3), pk2(v2 - bfh(v2), v3 - bfh(v3)));
    }
}

// ---------- launch ----------
extern "C" void kernel_launch(void* const* d_in, const int* in_sizes, int n_in,
                              void* d_out, int out_size) {
    const float* x          = (const float*)d_in[0];
    const int*   rpi        = (const int*)d_in[1];
    const float* mask       = (const float*)d_in[2];
    const float* sp_mask    = (const float*)d_in[3];
    const float* w_qkv      = (const float*)d_in[4];
    const float* b_qkv      = (const float*)d_in[5];
    const float* bias_table = (const float*)d_in[6];
    const float* w_proj     = (const float*)d_in[7];
    const float* b_proj     = (const float*)d_in[8];
    float* out = (float*)d_out;

    cudaFuncSetAttribute((const void*)qkv_mma_kernel,
                         cudaFuncAttributeMaxDynamicSharedMemorySize, MMA_SMEM);
    cudaFuncSetAttribute((const void*)proj_mma_kernel,
                         cudaFuncAttributeMaxDynamicSharedMemorySize, MMA_SMEM);
    cudaFuncSetAttribute((const void*)att_mma_kernel,
                         cudaFuncAttributeMaxDynamicSharedMemorySize, ATT_SMEM);

    prep_cmrp_kernel<<<4096, 256>>>(mask, sp_mask, rpi, bias_table);
    conv_w_kernel<<<24, 256>>>(w_qkv, 6144, 0);
    conv_w_kernel<<<8, 256>>>(w_proj, 2048, 1);
    qkv_mma_kernel<<<BWIN, 256, MMA_SMEM>>>(x, b_qkv);
    att_mma_kernel<<<dim3(BWIN, HEADS), 256, ATT_SMEM>>>(nullptr);
    proj_mma_kernel<<<BWIN, 256, MMA_SMEM>>>(b_proj, out);
}

// round 8
// speedup vs baseline: 2.6984x; 1.0318x over previous
#include <cuda_runtime.h>
#include <cuda_bf16.h>
#include <stdint.h>

#define DIM   128
#define HEADS 4
#define HD    32
#define NTOK  128
#define BWIN  2048
#define NMASK 256
#define SCALEF 0.1767766952966369f
#define PAD   136

// merged bias plane: mask + sp_mask + rpb per (w,h)
__device__ float g_cmrp[(size_t)NMASK * HEADS * NTOK * NTOK];
// split hi/lo bf16 planes: [b,h][t][16 uint32 = 32 bf16], 64B rows
__device__ uint32_t g_qph[(size_t)BWIN * HEADS * NTOK * 16];
__device__ uint32_t g_qpl[(size_t)BWIN * HEADS * NTOK * 16];
__device__ uint32_t g_kph[(size_t)BWIN * HEADS * NTOK * 16];
__device__ uint32_t g_kpl[(size_t)BWIN * HEADS * NTOK * 16];
__device__ uint32_t g_vph[(size_t)BWIN * HEADS * NTOK * 16];
__device__ uint32_t g_vpl[(size_t)BWIN * HEADS * NTOK * 16];
// packed ctx: [b][t][64 dpairs] uint2{hi01, lo01}
__device__ uint2 g_ctxp[(size_t)BWIN * NTOK * 64];
__device__ uint4 g_wqkv_h[6144], g_wqkv_l[6144];
__device__ uint4 g_wproj_h[2048], g_wproj_l[2048];

// ---------- helpers ----------
__device__ __forceinline__ uint32_t smem_u32(const void* p) {
    uint32_t a;
    asm("{ .reg .u64 t; cvta.to.shared.u64 t, %1; cvt.u32.u64 %0, t; }" : "=r"(a) : "l"(p));
    return a;
}
__device__ __forceinline__ uint32_t pk2(float a, float b) {
    __nv_bfloat162 t = __floats2bfloat162_rn(a, b);
    return *reinterpret_cast<uint32_t*>(&t);
}
__device__ __forceinline__ float bfh(float x) {
    return __bfloat162float(__float2bfloat16(x));
}
#define LDM4(r, addr) \
    asm volatile("ldmatrix.sync.aligned.m8n8.x4.shared.b16 {%0,%1,%2,%3}, [%4];" \
                 : "=r"((r)[0]), "=r"((r)[1]), "=r"((r)[2]), "=r"((r)[3]) : "r"(addr))
#define LDM4T(r, addr) \
    asm volatile("ldmatrix.sync.aligned.m8n8.x4.trans.shared.b16 {%0,%1,%2,%3}, [%4];" \
                 : "=r"((r)[0]), "=r"((r)[1]), "=r"((r)[2]), "=r"((r)[3]) : "r"(addr))
#define MMA(d, a, b0, b1) \
    asm volatile("mma.sync.aligned.m16n8k16.row.col.f32.bf16.bf16.f32 " \
                 "{%0,%1,%2,%3}, {%4,%5,%6,%7}, {%8,%9}, {%0,%1,%2,%3};" \
                 : "+f"((d)[0]), "+f"((d)[1]), "+f"((d)[2]), "+f"((d)[3]) \
                 : "r"((a)[0]), "r"((a)[1]), "r"((a)[2]), "r"((a)[3]), "r"(b0), "r"(b1))
#define STS2(addr, a, b) \
    asm volatile("st.shared.v2.b32 [%0], {%1, %2};" :: "r"(addr), "r"(a), "r"(b))
#define CPA16(dst, src) \
    asm volatile("cp.async.cg.shared.global [%0], [%1], 16;" :: "r"(dst), "l"(src))
#define CPA_COMMIT() asm volatile("cp.async.commit_group;" ::: "memory")
#define CPA_WAIT1()  asm volatile("cp.async.wait_group 1;" ::: "memory")
#define CPA_WAIT0()  asm volatile("cp.async.wait_group 0;" ::: "memory")

// gemm smem: A hi [0,34816) + A lo [34816,69632); reused as W double buffer
#define SM_XL 34816
#define GEMM_SMEM 69632

// ---------- prep ----------
__global__ void prep_cmrp_kernel(const float* __restrict__ m, const float* __restrict__ s,
                                 const int* __restrict__ rpi, const float* __restrict__ bt) {
    int gi = (blockIdx.x * 256 + threadIdx.x) * 4;
    int w = gi >> 14, i = gi & 16383;
    float4 a = *(const float4*)(m + (size_t)w * 16384 + i);
    float4 c = *(const float4*)(s + (size_t)w * 16384 + i);
    a.x += c.x; a.y += c.y; a.z += c.z; a.w += c.w;
    int4 r = *(const int4*)(rpi + i);
#pragma unroll
    for (int h = 0; h < HEADS; ++h) {
        float4 o = make_float4(a.x + __ldg(bt + r.x * 4 + h), a.y + __ldg(bt + r.y * 4 + h),
                               a.z + __ldg(bt + r.z * 4 + h), a.w + __ldg(bt + r.w * 4 + h));
        *(float4*)(g_cmrp + (((size_t)w * 4 + h) << 14) + i) = o;
    }
}
__global__ void conv_w_kernel(const float* __restrict__ w, int n, int which) {
    int i = blockIdx.x * 256 + threadIdx.x;
    if (i >= n) return;
    int row = i >> 4, c0 = (i & 15) * 8;
    const float* wr = w + row * DIM + c0;
    float4 v0 = *(const float4*)(wr), v1 = *(const float4*)(wr + 4);
    uint4 hv = make_uint4(pk2(v0.x, v0.y), pk2(v0.z, v0.w), pk2(v1.x, v1.y), pk2(v1.z, v1.w));
    uint4 lv = make_uint4(pk2(v0.x - bfh(v0.x), v0.y - bfh(v0.y)),
                          pk2(v0.z - bfh(v0.z), v0.w - bfh(v0.w)),
                          pk2(v1.x - bfh(v1.x), v1.y - bfh(v1.y)),
                          pk2(v1.z - bfh(v1.z), v1.w - bfh(v1.w)));
    if (which == 0) { g_wqkv_h[i] = hv; g_wqkv_l[i] = lv; }
    else            { g_wproj_h[i] = hv; g_wproj_l[i] = lv; }
}

// ---------- GEMM pieces ----------
__device__ __forceinline__ void conv_A(const float* __restrict__ src, uint32_t XH, int tid) {
    for (int i = tid; i < 4096; i += 256) {
        int t = i >> 5, c = (i & 31) * 4;
        float4 v = *(const float4*)(src + t * DIM + c);
        uint32_t o = XH + (uint32_t)(t * PAD + c) * 2u;
        STS2(o, pk2(v.x, v.y), pk2(v.z, v.w));
        STS2(o + SM_XL, pk2(v.x - bfh(v.x), v.y - bfh(v.y)),
             pk2(v.z - bfh(v.z), v.w - bfh(v.w)));
    }
}
__device__ __forceinline__ void fill_A_packed(const uint4* __restrict__ cp, uint32_t XH, int tid) {
    for (int i = tid; i < 4096; i += 256) {
        int t = i >> 5, p2 = i & 31;
        uint4 v = __ldg(cp + i);
        uint32_t o = XH + (uint32_t)(t * 272 + p2 * 8);
        STS2(o, v.x, v.z);
        STS2(o + SM_XL, v.y, v.w);
    }
}
// async-copy one W chunk (64 rows x 128 hi + lo) into buffer wb
__device__ __forceinline__ void cpW_async(const uint4* __restrict__ gh,
                                          const uint4* __restrict__ gl,
                                          uint32_t wb, int tid) {
    for (int i = tid; i < 1024; i += 256) {
        int row = i >> 4, c8 = i & 15;
        uint32_t o = wb + (uint32_t)(row * 272 + c8 * 16);
        CPA16(o, gh + i);
        CPA16(o + 17408, gl + i);
    }
}

// MODE 0: qkv epilogue (split hi/lo planes); MODE 1: proj (fp32 out + bias)
template <int NCHUNK, int MODE>
__device__ __forceinline__ void gemm_mma(const float* __restrict__ xsrc,
                                         const uint4* __restrict__ wh,
                                         const uint4* __restrict__ wl,
                                         const float* __restrict__ bias,
                                         float* __restrict__ gen_out, int b) {
    extern __shared__ unsigned char sraw[];
    uint32_t XH = smem_u32(sraw);
    int tid = threadIdx.x, wid = tid >> 5, lane = tid & 31;
    if (MODE == 0) conv_A(xsrc, XH, tid);
    else           fill_A_packed((const uint4*)g_ctxp + (size_t)b * 4096, XH, tid);
    __syncthreads();

    int r0 = wid * 16;
    int lr = lane & 15, kh = (lane >> 4) & 1;
    int brow = ((lane >> 4) & 1) * 8 + (lane & 7);
    int bseg = (lane >> 3) & 1;
    uint32_t abase = XH + (uint32_t)((r0 + lr) * PAD + kh * 8) * 2u;

    // hoist A fragments
    uint32_t ah[8][4], al[8][4];
#pragma unroll
    for (int k = 0; k < 8; ++k) {
        LDM4(ah[k], abase + (uint32_t)(k * 32));
        LDM4(al[k], abase + SM_XL + (uint32_t)(k * 32));
    }
    __syncthreads();   // A smem now dead -> becomes W double buffer

    cpW_async(wh, wl, XH, tid);
    CPA_COMMIT();
    if (NCHUNK > 1) { cpW_async(wh + 1024, wl + 1024, XH + 34816u, tid); CPA_COMMIT(); }

    for (int ch = 0; ch < NCHUNK; ++ch) {
        if (ch + 1 < NCHUNK) CPA_WAIT1(); else CPA_WAIT0();
        __syncthreads();
        uint32_t wb = XH + (uint32_t)((ch & 1) * 34816);
        uint32_t bbase = wb + (uint32_t)(brow * 272 + bseg * 16);

        float acc[8][4];
#pragma unroll
        for (int nt = 0; nt < 8; ++nt)
#pragma unroll
            for (int j = 0; j < 4; ++j) acc[nt][j] = 0.f;
#pragma unroll
        for (int k = 0; k < 8; ++k) {
#pragma unroll
            for (int ntp = 0; ntp < 4; ++ntp) {
                uint32_t ba = bbase + (uint32_t)(ntp * 16 * 272 + k * 32);
                uint32_t bh[4], bl[4];
                LDM4(bh, ba);
                LDM4(bl, ba + 17408);
                MMA(acc[2 * ntp],     ah[k], bh[0], bh[1]);
                MMA(acc[2 * ntp],     ah[k], bl[0], bl[1]);
                MMA(acc[2 * ntp],     al[k], bh[0], bh[1]);
                MMA(acc[2 * ntp + 1], ah[k], bh[2], bh[3]);
                MMA(acc[2 * ntp + 1], ah[k], bl[2], bl[3]);
                MMA(acc[2 * ntp + 1], al[k], bh[2], bh[3]);
            }
        }
        __syncthreads();   // all warps done reading wb
        if (ch + 2 < NCHUNK) { cpW_async(wh + (ch + 2) * 1024, wl + (ch + 2) * 1024, wb, tid); CPA_COMMIT(); }

        int t0 = r0 + (lane >> 2);
#pragma unroll
        for (int nt = 0; nt < 8; ++nt) {
            int f = ch * 64 + nt * 8 + (lane & 3) * 2;
            float bx = __ldg(bias + f), by = __ldg(bias + f + 1);
            if (MODE == 0) {
                int s = f >> 7, h = (f >> 5) & 3, dpair = (f & 31) >> 1;
                float sc = (s == 0) ? SCALEF : 1.0f;
                uint32_t* ph = (s == 0 ? g_qph : s == 1 ? g_kph : g_vph);
                uint32_t* pl = (s == 0 ? g_qpl : s == 1 ? g_kpl : g_vpl);
                size_t off = (((size_t)b * HEADS + h) * NTOK + t0) * 16 + dpair;
                float v0 = (acc[nt][0] + bx) * sc, v1 = (acc[nt][1] + by) * sc;
                ph[off] = pk2(v0, v1);
                pl[off] = pk2(v0 - bfh(v0), v1 - bfh(v1));
                float v2 = (acc[nt][2] + bx) * sc, v3 = (acc[nt][3] + by) * sc;
                ph[off + 8 * 16] = pk2(v2, v3);
                pl[off + 8 * 16] = pk2(v2 - bfh(v2), v3 - bfh(v3));
            } else {
                *(float2*)(gen_out + ((size_t)b * NTOK + t0) * DIM + f) =
                    make_float2(acc[nt][0] + bx, acc[nt][1] + by);
                *(float2*)(gen_out + ((size_t)b * NTOK + t0 + 8) * DIM + f) =
                    make_float2(acc[nt][2] + bx, acc[nt][3] + by);
            }
        }
    }
}
__global__ __launch_bounds__(256, 2)
void qkv_mma_kernel(const float* __restrict__ x, const float* __restrict__ b_qkv) {
    gemm_mma<6, 0>(x + (size_t)blockIdx.x * NTOK * DIM, g_wqkv_h, g_wqkv_l, b_qkv,
                   nullptr, blockIdx.x);
}
__global__ __launch_bounds__(256, 2)
void proj_mma_kernel(const float* __restrict__ b_proj, float* __restrict__ out) {
    gemm_mma<2, 1>(nullptr, g_wproj_h, g_wproj_l, b_proj, out, blockIdx.x);
}

// ---------- attention ----------
// smem planes, each [128 t][40 elems] bf16 = 10240 B
#define A_QH 0u
#define A_QL 10240u
#define A_KH 20480u
#define A_KL 30720u
#define A_VH 40960u
#define A_VL 51200u
#define ATT_SMEM 61440

__device__ __forceinline__ void cp_plane(uint32_t dst, const uint32_t* __restrict__ src, int tid) {
#pragma unroll
    for (int r = 0; r < 2; ++r) {
        int i = tid + r * 256;
        int t = i >> 2, seg = i & 3;
        CPA16(dst + (uint32_t)(t * 80 + seg * 16), src + (size_t)t * 16 + seg * 4);
    }
}

__global__ __launch_bounds__(256, 2)
void att_mma_kernel() {
    int b = blockIdx.x, h = blockIdx.y;
    extern __shared__ unsigned char sraw[];
    uint32_t sb = smem_u32(sraw);

    int tid = threadIdx.x, lane = tid & 31, wid = tid >> 5;
    size_t pbase = ((size_t)b * HEADS + h) * (NTOK * 16);

    cp_plane(sb + A_QH, g_qph + pbase, tid);
    cp_plane(sb + A_QL, g_qpl + pbase, tid);
    cp_plane(sb + A_KH, g_kph + pbase, tid);
    cp_plane(sb + A_KL, g_kpl + pbase, tid);
    cp_plane(sb + A_VH, g_vph + pbase, tid);
    cp_plane(sb + A_VL, g_vpl + pbase, tid);
    CPA_COMMIT();
    CPA_WAIT0();
    __syncthreads();

    int r0 = wid * 16;
    int lr = lane & 15, khf = (lane >> 4) & 1;
    int brow = ((lane >> 4) & 1) * 8 + (lane & 7);
    int bseg = (lane >> 3) & 1;
    uint32_t qa = sb + A_QH + (uint32_t)((r0 + lr) * 80 + khf * 16);
    uint32_t ka = sb + A_KH + (uint32_t)(brow * 80 + bseg * 16);
    int vrow = (lane & 7) + ((lane >> 3) & 1) * 8;
    uint32_t va = sb + A_VH + (uint32_t)(vrow * 80 + ((lane >> 4) & 1) * 16);

    uint32_t ah[2][4], al[2][4];
#pragma unroll
    for (int k = 0; k < 2; ++k) {
        LDM4(ah[k], qa + (uint32_t)(k * 32));
        LDM4(al[k], qa + (A_QL - A_QH) + (uint32_t)(k * 32));
    }

    // ---- S = q k^T ----
    float sacc[16][4];
#pragma unroll
    for (int j = 0; j < 16; ++j)
#pragma unroll
        for (int c = 0; c < 4; ++c) sacc[j][c] = 0.f;
#pragma unroll
    for (int ntp = 0; ntp < 8; ++ntp) {
#pragma unroll
        for (int k = 0; k < 2; ++k) {
            uint32_t ba = ka + (uint32_t)(ntp * 16 * 80 + k * 32);
            uint32_t bh[4], bl[4];
            LDM4(bh, ba);
            LDM4(bl, ba + (A_KL - A_KH));
            MMA(sacc[2 * ntp],     ah[k], bh[0], bh[1]);
            MMA(sacc[2 * ntp],     ah[k], bl[0], bl[1]);
            MMA(sacc[2 * ntp],     al[k], bh[0], bh[1]);
            MMA(sacc[2 * ntp + 1], ah[k], bh[2], bh[3]);
            MMA(sacc[2 * ntp + 1], ah[k], bl[2], bl[3]);
            MMA(sacc[2 * ntp + 1], al[k], bh[2], bh[3]);
        }
    }

    // ---- merged bias ----
    int g = lane >> 2, q2 = (lane & 3) * 2;
    int row0 = r0 + g;
    const float* cm = g_cmrp + (((size_t)(b & (NMASK - 1)) * HEADS + h) << 14)
                    + row0 * NTOK + q2;
#pragma unroll
    for (int j = 0; j < 16; ++j) {
        float2 c0 = *(const float2*)(cm + j * 8);
        float2 c1 = *(const float2*)(cm + 8 * NTOK + j * 8);
        sacc[j][0] += c0.x;  sacc[j][1] += c0.y;
        sacc[j][2] += c1.x;  sacc[j][3] += c1.y;
    }

    // ---- softmax ----
    float mx0 = -1e30f, mx1 = -1e30f;
#pragma unroll
    for (int j = 0; j < 16; ++j) {
        mx0 = fmaxf(mx0, fmaxf(sacc[j][0], sacc[j][1]));
        mx1 = fmaxf(mx1, fmaxf(sacc[j][2], sacc[j][3]));
    }
    mx0 = fmaxf(mx0, __shfl_xor_sync(0xffffffffu, mx0, 1));
    mx0 = fmaxf(mx0, __shfl_xor_sync(0xffffffffu, mx0, 2));
    mx1 = fmaxf(mx1, __shfl_xor_sync(0xffffffffu, mx1, 1));
    mx1 = fmaxf(mx1, __shfl_xor_sync(0xffffffffu, mx1, 2));
    float s0 = 0.f, s1 = 0.f;
#pragma unroll
    for (int j = 0; j < 16; ++j) {
        sacc[j][0] = __expf(sacc[j][0] - mx0);
        sacc[j][1] = __expf(sacc[j][1] - mx0);
        sacc[j][2] = __expf(sacc[j][2] - mx1);
        sacc[j][3] = __expf(sacc[j][3] - mx1);
        s0 += sacc[j][0] + sacc[j][1];
        s1 += sacc[j][2] + sacc[j][3];
    }
    s0 += __shfl_xor_sync(0xffffffffu, s0, 1);
    s0 += __shfl_xor_sync(0xffffffffu, s0, 2);
    s1 += __shfl_xor_sync(0xffffffffu, s1, 1);
    s1 += __shfl_xor_sync(0xffffffffu, s1, 2);
    float inv0 = 1.0f / s0, inv1 = 1.0f / s1;

    // ---- PV ----
    float oacc[4][4];
#pragma unroll
    for (int dn = 0; dn < 4; ++dn)
#pragma unroll
        for (int c = 0; c < 4; ++c) oacc[dn][c] = 0.f;
#pragma unroll
    for (int kk = 0; kk < 8; ++kk) {
        float p00 = sacc[2 * kk][0],     p01 = sacc[2 * kk][1];
        float p10 = sacc[2 * kk][2],     p11 = sacc[2 * kk][3];
        float p20 = sacc[2 * kk + 1][0], p21 = sacc[2 * kk + 1][1];
        float p30 = sacc[2 * kk + 1][2], p31 = sacc[2 * kk + 1][3];
        uint32_t aH[4], aL[4];
        aH[0] = pk2(p00, p01); aH[1] = pk2(p10, p11);
        aH[2] = pk2(p20, p21); aH[3] = pk2(p30, p31);
        aL[0] = pk2(p00 - bfh(p00), p01 - bfh(p01));
        aL[1] = pk2(p10 - bfh(p10), p11 - bfh(p11));
        aL[2] = pk2(p20 - bfh(p20), p21 - bfh(p21));
        aL[3] = pk2(p30 - bfh(p30), p31 - bfh(p31));
#pragma unroll
        for (int dnp = 0; dnp < 2; ++dnp) {
            uint32_t ba = va + (uint32_t)(kk * 16 * 80 + dnp * 32);
            uint32_t bh[4], bl[4];
            LDM4T(bh, ba);
            LDM4T(bl, ba + (A_VL - A_VH));
            MMA(oacc[2 * dnp],     aH, bh[0], bh[1]);
            MMA(oacc[2 * dnp],     aH, bl[0], bl[1]);
            MMA(oacc[2 * dnp],     aL, bh[0], bh[1]);
            MMA(oacc[2 * dnp + 1], aH, bh[2], bh[3]);
            MMA(oacc[2 * dnp + 1], aH, bl[2], bl[3]);
            MMA(oacc[2 * dnp + 1], aL, bh[2], bh[3]);
        }
    }

    uint2* cp0 = g_ctxp + ((size_t)b * NTOK + row0) * 64 + h * 16 + (lane & 3);
#pragma unroll
    for (int dn = 0; dn < 4; ++dn) {
        float v0 = oacc[dn][0] * inv0, v1 = oacc[dn][1] * inv0;
        cp0[dn * 4] = make_uint2(pk2(v0, v1), pk2(v0 - bfh(v0), v1 - bfh(v1)));
        float v2 = oacc[dn][2] * inv1, v3 = oacc[dn][3] * inv1;
        cp0[8 * 64 + dn * 4] = make_uint2(pk2(v2, v3), pk2(v2 - bfh(v2), v3 - bfh(v3)));
    }
}

// ---------- launch ----------
extern "C" void kernel_launch(void* const* d_in, const int* in_sizes, int n_in,
                              void* d_out, int out_size) {
    const float* x          = (const float*)d_in[0];
    const int*   rpi        = (const int*)d_in[1];
    const float* mask       = (const float*)d_in[2];
    const float* sp_mask    = (const float*)d_in[3];
    const float* w_qkv      = (const float*)d_in[4];
    const float* b_qkv      = (const float*)d_in[5];
    const float* bias_table = (const float*)d_in[6];
    const float* w_proj     = (const float*)d_in[7];
    const float* b_proj     = (const float*)d_in[8];
    float* out = (float*)d_out;

    cudaFuncSetAttribute((const void*)qkv_mma_kernel,
                         cudaFuncAttributeMaxDynamicSharedMemorySize, GEMM_SMEM);
    cudaFuncSetAttribute((const void*)proj_mma_kernel,
                         cudaFuncAttributeMaxDynamicSharedMemorySize, GEMM_SMEM);
    cudaFuncSetAttribute((const void*)att_mma_kernel,
                         cudaFuncAttributeMaxDynamicSharedMemorySize, ATT_SMEM);

    prep_cmrp_kernel<<<4096, 256>>>(mask, sp_mask, rpi, bias_table);
    conv_w_kernel<<<24, 256>>>(w_qkv, 6144, 0);
    conv_w_kernel<<<8, 256>>>(w_proj, 2048, 1);
    qkv_mma_kernel<<<BWIN, 256, GEMM_SMEM>>>(x, b_qkv);
    att_mma_kernel<<<dim3(BWIN, HEADS), 256, ATT_SMEM>>>();
    proj_mma_kernel<<<BWIN, 256, GEMM_SMEM>>>(b_proj, out);
}